// round 4
// baseline (speedup 1.0000x reference)
#include <cuda_runtime.h>
#include <math.h>

// Problem constants
#define Bc   2
#define Sc   2048
#define Ec   1024
#define Hc   16
#define HDc  64
#define Mrows (Bc*Sc)          // 4096
#define NEGBIG (-1.0e9f)

// Scratch (device globals; no allocation allowed)
__device__ float g_q[Bc*Hc*Sc*HDc];     // [B,H,S,HD]
__device__ float g_k[Bc*Hc*Sc*HDc];
__device__ float g_v[Bc*Hc*Sc*HDc];
__device__ float g_vals[Mrows*Ec];      // [B,S,E]

// ---------------------------------------------------------------------------
// GEMM: C[m][n] = sum_k A[m][k] * W[n][k] + bias[n]
// A row-major [M,K], W row-major [N,K] (i.e. x @ W.T + b, torch Linear).
// mode 0: scatter into g_q/g_k/g_v per the qkv reshape/transpose/split.
// mode 1: plain row-major store to Cplain [M,N].
// Tile 64x64, K-tile 16, 256 threads, 4x4 per thread (N mapped tx+16j).
// ---------------------------------------------------------------------------
__global__ void gemm_kernel(const float* __restrict__ A,
                            const float* __restrict__ W,
                            const float* __restrict__ bias,
                            float* __restrict__ Cplain,
                            int Kdim, int Ncols, int mode)
{
    __shared__ float As[64][17];
    __shared__ float Ws[64][17];

    const int tid = threadIdx.x;
    const int tx  = tid & 15;
    const int ty  = tid >> 4;
    const int m0  = blockIdx.x << 6;
    const int n0  = blockIdx.y << 6;

    float acc[4][4] = {};

    const int lrow = tid >> 2;          // 0..63
    const int lseg = (tid & 3) << 2;    // 0,4,8,12
    const float* Arow = A + (size_t)(m0 + lrow) * Kdim + lseg;
    const float* Wrow = W + (size_t)(n0 + lrow) * Kdim + lseg;

    for (int k0 = 0; k0 < Kdim; k0 += 16) {
        float4 av = *reinterpret_cast<const float4*>(Arow + k0);
        float4 wv = *reinterpret_cast<const float4*>(Wrow + k0);
        As[lrow][lseg+0] = av.x; As[lrow][lseg+1] = av.y;
        As[lrow][lseg+2] = av.z; As[lrow][lseg+3] = av.w;
        Ws[lrow][lseg+0] = wv.x; Ws[lrow][lseg+1] = wv.y;
        Ws[lrow][lseg+2] = wv.z; Ws[lrow][lseg+3] = wv.w;
        __syncthreads();

        #pragma unroll
        for (int kk = 0; kk < 16; kk++) {
            float a[4], w[4];
            #pragma unroll
            for (int i = 0; i < 4; i++) a[i] = As[ty*4 + i][kk];
            #pragma unroll
            for (int j = 0; j < 4; j++) w[j] = Ws[tx + 16*j][kk];
            #pragma unroll
            for (int i = 0; i < 4; i++)
                #pragma unroll
                for (int j = 0; j < 4; j++)
                    acc[i][j] = fmaf(a[i], w[j], acc[i][j]);
        }
        __syncthreads();
    }

    #pragma unroll
    for (int i = 0; i < 4; i++) {
        const int m = m0 + ty*4 + i;
        #pragma unroll
        for (int j = 0; j < 4; j++) {
            const int n = n0 + tx + 16*j;
            const float c = acc[i][j] + bias[n];
            if (mode == 0) {
                // qkv[b,s,n] ; n -> h = n/192, r = n%192, part = r/64, d = r%64
                const int h    = n / 192;
                const int r    = n - h * 192;
                const int part = r >> 6;
                const int d    = r & 63;
                const int b    = m >> 11;    // S = 2048
                const int s    = m & 2047;
                const int idx  = (((b*Hc + h) * Sc) + s) * HDc + d;
                float* dst = (part == 0) ? g_q : (part == 1) ? g_k : g_v;
                dst[idx] = c;
            } else {
                Cplain[(size_t)m * Ncols + n] = c;
            }
        }
    }
}

// ---------------------------------------------------------------------------
// Flash attention with the reference's tril*NEG_INF mask (masks k <= q).
// One block per (q-tile of 64, b*h). Online softmax, 64x64 K-tiles.
// Tile-skip: rows q attend only k > q, so k-tiles with jk < jq are exact
// zeros after renormalization -> skip. Exception: the last q-tile contains
// q = S-1 (fully masked row -> softmax over ALL keys via shift invariance),
// so it scans every k-tile to match the reference bit-for-bit in behavior.
// ---------------------------------------------------------------------------
__global__ void attn_kernel()
{
    extern __shared__ float sm[];
    float* Qs = sm;                 // [64][65]
    float* Ks = sm + 64*65;         // [64][65]
    float* Vs = sm + 2*64*65;       // [64][65]
    float* Ps = sm + 3*64*65;       // [64][65]

    const int tid = threadIdx.x;
    const int tx  = tid & 15;
    const int ty  = tid >> 4;
    const int jq  = blockIdx.x;     // 0..31
    const int bh  = blockIdx.y;     // 0..31

    const float* Qg = g_q + (size_t)bh * Sc * HDc;
    const float* Kg = g_k + (size_t)bh * Sc * HDc;
    const float* Vg = g_v + (size_t)bh * Sc * HDc;

    // Load Q tile (64x64)
    #pragma unroll
    for (int it = 0; it < 4; it++) {
        const int i  = tid + it*256;
        const int r  = i >> 4;
        const int cs = (i & 15) << 2;
        float4 v = *reinterpret_cast<const float4*>(&Qg[(jq*64 + r)*64 + cs]);
        Qs[r*65 + cs+0] = v.x; Qs[r*65 + cs+1] = v.y;
        Qs[r*65 + cs+2] = v.z; Qs[r*65 + cs+3] = v.w;
    }

    float m_i[4], l_i[4], acc[4][4];
    #pragma unroll
    for (int i = 0; i < 4; i++) {
        m_i[i] = -INFINITY; l_i[i] = 0.0f;
        #pragma unroll
        for (int j = 0; j < 4; j++) acc[i][j] = 0.0f;
    }

    const int r0 = ty * 4;
    const int kstart = (jq == (Sc/64 - 1)) ? 0 : jq;

    for (int jk = kstart; jk < Sc/64; jk++) {
        __syncthreads();   // prior-iter smem reads done (also covers Q load on iter 1)
        #pragma unroll
        for (int it = 0; it < 4; it++) {
            const int i  = tid + it*256;
            const int r  = i >> 4;
            const int cs = (i & 15) << 2;
            float4 kv = *reinterpret_cast<const float4*>(&Kg[(jk*64 + r)*64 + cs]);
            Ks[r*65 + cs+0] = kv.x; Ks[r*65 + cs+1] = kv.y;
            Ks[r*65 + cs+2] = kv.z; Ks[r*65 + cs+3] = kv.w;
            float4 vv = *reinterpret_cast<const float4*>(&Vg[(jk*64 + r)*64 + cs]);
            Vs[r*65 + cs+0] = vv.x; Vs[r*65 + cs+1] = vv.y;
            Vs[r*65 + cs+2] = vv.z; Vs[r*65 + cs+3] = vv.w;
        }
        __syncthreads();

        // S = Q K^T  (64x64x64)
        float sv[4][4] = {};
        #pragma unroll 8
        for (int kk = 0; kk < 64; kk++) {
            float a[4], bb[4];
            #pragma unroll
            for (int i = 0; i < 4; i++) a[i]  = Qs[(r0 + i)*65 + kk];
            #pragma unroll
            for (int j = 0; j < 4; j++) bb[j] = Ks[(tx + 16*j)*65 + kk];
            #pragma unroll
            for (int i = 0; i < 4; i++)
                #pragma unroll
                for (int j = 0; j < 4; j++)
                    sv[i][j] = fmaf(a[i], bb[j], sv[i][j]);
        }

        // scale + mask (tril incl. diagonal gets -1e9, faithful to source)
        const int qbase = jq*64 + r0;
        const int kbase = jk*64 + tx;
        #pragma unroll
        for (int i = 0; i < 4; i++)
            #pragma unroll
            for (int j = 0; j < 4; j++)
                sv[i][j] = sv[i][j] * 0.125f +
                           ((kbase + 16*j) <= (qbase + i) ? NEGBIG : 0.0f);

        // online softmax (row groups of 16 lanes: tx; xor-shfl within 16)
        #pragma unroll
        for (int i = 0; i < 4; i++) {
            float rm = fmaxf(fmaxf(sv[i][0], sv[i][1]), fmaxf(sv[i][2], sv[i][3]));
            rm = fmaxf(rm, __shfl_xor_sync(0xffffffffu, rm, 8));
            rm = fmaxf(rm, __shfl_xor_sync(0xffffffffu, rm, 4));
            rm = fmaxf(rm, __shfl_xor_sync(0xffffffffu, rm, 2));
            rm = fmaxf(rm, __shfl_xor_sync(0xffffffffu, rm, 1));
            const float mn = fmaxf(m_i[i], rm);
            const float sc = __expf(m_i[i] - mn);
            l_i[i] *= sc;
            float rs = 0.0f;
            #pragma unroll
            for (int j = 0; j < 4; j++) {
                acc[i][j] *= sc;
                sv[i][j] = __expf(sv[i][j] - mn);
                rs += sv[i][j];
            }
            rs += __shfl_xor_sync(0xffffffffu, rs, 8);
            rs += __shfl_xor_sync(0xffffffffu, rs, 4);
            rs += __shfl_xor_sync(0xffffffffu, rs, 2);
            rs += __shfl_xor_sync(0xffffffffu, rs, 1);
            l_i[i] += rs;
            m_i[i]  = mn;
        }

        // P -> smem
        #pragma unroll
        for (int i = 0; i < 4; i++)
            #pragma unroll
            for (int j = 0; j < 4; j++)
                Ps[(r0 + i)*65 + tx + 16*j] = sv[i][j];
        __syncthreads();

        // acc += P V  (64x64x64)
        #pragma unroll 8
        for (int kk = 0; kk < 64; kk++) {
            float p[4], vv[4];
            #pragma unroll
            for (int i = 0; i < 4; i++) p[i]  = Ps[(r0 + i)*65 + kk];
            #pragma unroll
            for (int j = 0; j < 4; j++) vv[j] = Vs[kk*65 + tx + 16*j];
            #pragma unroll
            for (int i = 0; i < 4; i++)
                #pragma unroll
                for (int j = 0; j < 4; j++)
                    acc[i][j] = fmaf(p[i], vv[j], acc[i][j]);
        }
    }

    // normalize + write vals in [B,S,E] layout (E index = h*64 + d)
    const int b = bh >> 4;
    const int h = bh & 15;
    #pragma unroll
    for (int i = 0; i < 4; i++) {
        const float inv = 1.0f / l_i[i];
        const int q = jq*64 + r0 + i;
        const size_t base = ((size_t)(b*Sc + q)) * Ec + h*HDc + tx;
        #pragma unroll
        for (int j = 0; j < 4; j++)
            g_vals[base + 16*j] = acc[i][j] * inv;
    }
}

// ---------------------------------------------------------------------------
extern "C" void kernel_launch(void* const* d_in, const int* in_sizes, int n_in,
                              void* d_out, int out_size)
{
    const float* x    = (const float*)d_in[0];
    const float* Wqkv = (const float*)d_in[1];
    const float* bqkv = (const float*)d_in[2];
    const float* Wout = (const float*)d_in[3];
    const float* bout = (const float*)d_in[4];
    float* out = (float*)d_out;

    float* valsp = nullptr;
    cudaGetSymbolAddress((void**)&valsp, g_vals);

    const dim3 blk(256);

    // 1) QKV projection, scattered into [B,H,S,HD] q/k/v buffers
    gemm_kernel<<<dim3(Mrows/64, (3*Ec)/64), blk>>>(
        x, Wqkv, bqkv, nullptr, Ec, 3*Ec, 0);

    // 2) Attention -> g_vals [B,S,E]
    const int smem = 4 * 64 * 65 * (int)sizeof(float);   // 66,560 B
    cudaFuncSetAttribute(attn_kernel,
                         cudaFuncAttributeMaxDynamicSharedMemorySize, smem);
    attn_kernel<<<dim3(Sc/64, Bc*Hc), blk, smem>>>();

    // 3) Output projection -> d_out [B,S,E]
    gemm_kernel<<<dim3(Mrows/64, Ec/64), blk>>>(
        valsp, Wout, bout, out, Ec, Ec, 1);
}

// round 5
// speedup vs baseline: 1.9501x; 1.9501x over previous
#include <cuda_runtime.h>
#include <math.h>
#include <stdint.h>

// Problem constants
#define Bc   2
#define Sc   2048
#define Ec   1024
#define Hc   16
#define HDc  64
#define Mrows (Bc*Sc)          // 4096
#define NEGBIG (-1.0e9f)

// Scratch (device globals; no allocation allowed)
__device__ float g_q[Bc*Hc*Sc*HDc];     // [B,H,S,HD]
__device__ float g_k[Bc*Hc*Sc*HDc];
__device__ float g_v[Bc*Hc*Sc*HDc];
__device__ float g_vals[Mrows*Ec];      // [B,S,E]

// ---------------------------------------------------------------------------
// tf32 helpers
// ---------------------------------------------------------------------------
__device__ __forceinline__ uint32_t f2tf(float x) {
    uint32_t r;
    asm("cvt.rna.tf32.f32 %0, %1;" : "=r"(r) : "f"(x));
    return r;
}

__device__ __forceinline__ void mma8(float* c,
    uint32_t a0, uint32_t a1, uint32_t a2, uint32_t a3,
    uint32_t b0, uint32_t b1)
{
    asm volatile(
        "mma.sync.aligned.m16n8k8.row.col.f32.tf32.tf32.f32 "
        "{%0,%1,%2,%3},{%4,%5,%6,%7},{%8,%9},{%0,%1,%2,%3};"
        : "+f"(c[0]), "+f"(c[1]), "+f"(c[2]), "+f"(c[3])
        : "r"(a0), "r"(a1), "r"(a2), "r"(a3), "r"(b0), "r"(b1));
}

// ---------------------------------------------------------------------------
// tf32 tensor-core GEMM: C[m][n] = sum_k A[m][k]*W[n][k] + bias[n]
// Block tile 128x128, K-tile 32, 256 threads (8 warps, 2x4), warp tile 64x32.
// smem stride 36 floats: frag-load banks = (4g + tg) mod 32 -> conflict-free;
// 36 floats = 144 B (16B multiple) -> uint4 tile stores are aligned and land
// 128B-contiguous per quarter-warp phase -> conflict-free stores.
// SPLIT: 2-term tf32 decomposition (hi + lo), 3 MMAs -> fp32-grade accuracy.
// MODE 0: scatter epilogue into g_q/g_k/g_v; MODE 1: plain store.
// ---------------------------------------------------------------------------
#define GSK 36

template<int MODE, bool SPLIT>
__global__ __launch_bounds__(256) void gemm_tf32(
    const float* __restrict__ A, const float* __restrict__ W,
    const float* __restrict__ bias, float* __restrict__ Cplain,
    int Kdim, int Ncols)
{
    extern __shared__ uint32_t smb[];
    uint32_t* Ah = smb;                       // 128*36
    uint32_t* Wh = Ah + 128*GSK;
    uint32_t* Al = SPLIT ? (Wh + 128*GSK) : nullptr;
    uint32_t* Wl = SPLIT ? (Al + 128*GSK) : nullptr;

    const int tid  = threadIdx.x;
    const int lane = tid & 31, w = tid >> 5;
    const int g = lane >> 2, tg = lane & 3;
    const int wm = w & 1, wn = w >> 1;
    const int m0 = blockIdx.x << 7, n0 = blockIdx.y << 7;

    float acc[4][4][4];
    #pragma unroll
    for (int i = 0; i < 4; i++)
        #pragma unroll
        for (int j = 0; j < 4; j++)
            #pragma unroll
            for (int r = 0; r < 4; r++) acc[i][j][r] = 0.0f;

    const int lr = tid >> 3;           // 0..31
    const int lc = (tid & 7) << 2;     // 0..28

    for (int k0 = 0; k0 < Kdim; k0 += 32) {
        #pragma unroll
        for (int p = 0; p < 4; p++) {
            const int row = lr + p*32;
            float4 av = *reinterpret_cast<const float4*>(A + (size_t)(m0+row)*Kdim + k0 + lc);
            float4 wv = *reinterpret_cast<const float4*>(W + (size_t)(n0+row)*Kdim + k0 + lc);
            uint32_t ah0=f2tf(av.x), ah1=f2tf(av.y), ah2=f2tf(av.z), ah3=f2tf(av.w);
            uint32_t wh0=f2tf(wv.x), wh1=f2tf(wv.y), wh2=f2tf(wv.z), wh3=f2tf(wv.w);
            *reinterpret_cast<uint4*>(&Ah[row*GSK + lc]) = make_uint4(ah0,ah1,ah2,ah3);
            *reinterpret_cast<uint4*>(&Wh[row*GSK + lc]) = make_uint4(wh0,wh1,wh2,wh3);
            if (SPLIT) {
                uint32_t al0=f2tf(av.x-__uint_as_float(ah0)), al1=f2tf(av.y-__uint_as_float(ah1));
                uint32_t al2=f2tf(av.z-__uint_as_float(ah2)), al3=f2tf(av.w-__uint_as_float(ah3));
                uint32_t wl0=f2tf(wv.x-__uint_as_float(wh0)), wl1=f2tf(wv.y-__uint_as_float(wh1));
                uint32_t wl2=f2tf(wv.z-__uint_as_float(wh2)), wl3=f2tf(wv.w-__uint_as_float(wh3));
                *reinterpret_cast<uint4*>(&Al[row*GSK + lc]) = make_uint4(al0,al1,al2,al3);
                *reinterpret_cast<uint4*>(&Wl[row*GSK + lc]) = make_uint4(wl0,wl1,wl2,wl3);
            }
        }
        __syncthreads();

        #pragma unroll
        for (int ks = 0; ks < 4; ks++) {
            const int kk = ks*8;
            uint32_t bh[4][2], bl[4][2];
            #pragma unroll
            for (int j = 0; j < 4; j++) {
                const int n = (wn*32 + j*8 + g)*GSK + kk + tg;
                bh[j][0] = Wh[n]; bh[j][1] = Wh[n+4];
                if (SPLIT) { bl[j][0] = Wl[n]; bl[j][1] = Wl[n+4]; }
            }
            #pragma unroll
            for (int i = 0; i < 4; i++) {
                const int mr = (wm*64 + i*16 + g)*GSK + kk + tg;
                uint32_t a0 = Ah[mr],           a1 = Ah[mr + 8*GSK];
                uint32_t a2 = Ah[mr + 4],       a3 = Ah[mr + 8*GSK + 4];
                uint32_t l0=0, l1=0, l2=0, l3=0;
                if (SPLIT) {
                    l0 = Al[mr];     l1 = Al[mr + 8*GSK];
                    l2 = Al[mr + 4]; l3 = Al[mr + 8*GSK + 4];
                }
                #pragma unroll
                for (int j = 0; j < 4; j++) {
                    mma8(acc[i][j], a0,a1,a2,a3, bh[j][0], bh[j][1]);
                    if (SPLIT) {
                        mma8(acc[i][j], a0,a1,a2,a3, bl[j][0], bl[j][1]);
                        mma8(acc[i][j], l0,l1,l2,l3, bh[j][0], bh[j][1]);
                    }
                }
            }
        }
        __syncthreads();
    }

    // Epilogue: c0 (r,2tg) c1 (r,2tg+1) c2 (r+8,2tg) c3 (r+8,2tg+1)
    #pragma unroll
    for (int i = 0; i < 4; i++) {
        const int mlo = m0 + wm*64 + i*16 + g;
        #pragma unroll
        for (int j = 0; j < 4; j++) {
            const int n = n0 + wn*32 + j*8 + 2*tg;
            const float b0 = __ldg(&bias[n]), b1 = __ldg(&bias[n+1]);
            #pragma unroll
            for (int half = 0; half < 2; half++) {
                const int m = mlo + half*8;
                const float v0 = acc[i][j][half*2+0] + b0;
                const float v1 = acc[i][j][half*2+1] + b1;
                if (MODE == 0) {
                    const int h = n / 192, r = n - h*192;
                    const int part = r >> 6, d = r & 63;
                    const int b = m >> 11, s = m & 2047;
                    float* dst = (part == 0) ? g_q : (part == 1) ? g_k : g_v;
                    *reinterpret_cast<float2*>(&dst[(((b*Hc + h)*Sc) + s)*HDc + d]) =
                        make_float2(v0, v1);
                } else {
                    *reinterpret_cast<float2*>(&Cplain[(size_t)m*Ncols + n]) =
                        make_float2(v0, v1);
                }
            }
        }
    }
}

// ---------------------------------------------------------------------------
// Flash attention, tf32 tensor cores. BQ=128 q-rows/block, K-tiles of 64.
// 8 warps; warp tile m16 x n64 (rows fully within one warp -> warp-local
// online softmax). P round-trips through smem per warp (no cross-warp dep,
// __syncwarp only). smem stride 68 floats (272B, 16B-mult): frag loads
// conflict-free, uint4 tile stores aligned + conflict-free.
// Mask = tril incl diagonal gets -1e9 (faithful: masks k <= q).
// ---------------------------------------------------------------------------
#define AST 68
#define BQ  128
#define TK  64

__global__ __launch_bounds__(256) void attn_tf32()
{
    extern __shared__ uint32_t sm[];
    uint32_t* Qs = sm;                  // BQ*AST
    uint32_t* Ks = Qs + BQ*AST;         // TK*AST
    uint32_t* Vs = Ks + TK*AST;         // TK*AST
    uint32_t* Ps = Vs + TK*AST;         // BQ*AST

    const int tid  = threadIdx.x;
    const int lane = tid & 31, w = tid >> 5;
    const int g = lane >> 2, tg = lane & 3;
    const int jq = blockIdx.x;          // 0..15
    const int bh = blockIdx.y;          // 0..31

    const float* Qg = g_q + (size_t)bh * Sc * HDc;
    const float* Kg = g_k + (size_t)bh * Sc * HDc;
    const float* Vg = g_v + (size_t)bh * Sc * HDc;

    // Load Q tile (128 x 64)
    #pragma unroll
    for (int p = 0; p < 8; p++) {
        const int idx = tid + p*256;
        const int r = idx >> 4, c = (idx & 15) << 2;
        float4 v = *reinterpret_cast<const float4*>(Qg + (size_t)(jq*BQ + r)*HDc + c);
        *reinterpret_cast<uint4*>(&Qs[r*AST + c]) =
            make_uint4(f2tf(v.x), f2tf(v.y), f2tf(v.z), f2tf(v.w));
    }

    float m_i[2] = {-INFINITY, -INFINITY};
    float l_i[2] = {0.0f, 0.0f};
    float O[8][4];
    #pragma unroll
    for (int j = 0; j < 8; j++)
        #pragma unroll
        for (int r = 0; r < 4; r++) O[j][r] = 0.0f;

    const int r0 = w * 16;
    const int kstart = (jq == (Sc/BQ - 1)) ? 0 : 2*jq;

    for (int jk = kstart; jk < Sc/TK; jk++) {
        __syncthreads();   // prior-iter K/V reads done (covers Q load on iter 1)
        #pragma unroll
        for (int p = 0; p < 4; p++) {
            const int idx = tid + p*256;
            const int r = idx >> 4, c = (idx & 15) << 2;
            float4 kv = *reinterpret_cast<const float4*>(Kg + (size_t)(jk*TK + r)*HDc + c);
            float4 vv = *reinterpret_cast<const float4*>(Vg + (size_t)(jk*TK + r)*HDc + c);
            *reinterpret_cast<uint4*>(&Ks[r*AST + c]) =
                make_uint4(f2tf(kv.x), f2tf(kv.y), f2tf(kv.z), f2tf(kv.w));
            *reinterpret_cast<uint4*>(&Vs[r*AST + c]) =
                make_uint4(f2tf(vv.x), f2tf(vv.y), f2tf(vv.z), f2tf(vv.w));
        }
        __syncthreads();

        // S = Q K^T : warp rows r0..r0+15, all 64 cols
        float S[8][4];
        #pragma unroll
        for (int j = 0; j < 8; j++)
            #pragma unroll
            for (int r = 0; r < 4; r++) S[j][r] = 0.0f;

        #pragma unroll
        for (int ks = 0; ks < 8; ks++) {
            const int kk = ks*8;
            const int ar = (r0 + g)*AST + kk + tg;
            uint32_t a0 = Qs[ar],     a1 = Qs[ar + 8*AST];
            uint32_t a2 = Qs[ar + 4], a3 = Qs[ar + 8*AST + 4];
            #pragma unroll
            for (int j = 0; j < 8; j++) {
                const int br = (j*8 + g)*AST + kk + tg;
                mma8(S[j], a0,a1,a2,a3, Ks[br], Ks[br + 4]);
            }
        }

        // scale + mask
        const int qlo = jq*BQ + r0 + g, qhi = qlo + 8;
        #pragma unroll
        for (int j = 0; j < 8; j++) {
            const int c0 = jk*TK + j*8 + 2*tg;
            S[j][0] = S[j][0]*0.125f + ((c0    ) <= qlo ? NEGBIG : 0.0f);
            S[j][1] = S[j][1]*0.125f + ((c0 + 1) <= qlo ? NEGBIG : 0.0f);
            S[j][2] = S[j][2]*0.125f + ((c0    ) <= qhi ? NEGBIG : 0.0f);
            S[j][3] = S[j][3]*0.125f + ((c0 + 1) <= qhi ? NEGBIG : 0.0f);
        }

        // online softmax (rows live in lanes sharing g; reduce over tg via xor)
        float rm0 = -INFINITY, rm1 = -INFINITY;
        #pragma unroll
        for (int j = 0; j < 8; j++) {
            rm0 = fmaxf(rm0, fmaxf(S[j][0], S[j][1]));
            rm1 = fmaxf(rm1, fmaxf(S[j][2], S[j][3]));
        }
        rm0 = fmaxf(rm0, __shfl_xor_sync(0xffffffffu, rm0, 1));
        rm0 = fmaxf(rm0, __shfl_xor_sync(0xffffffffu, rm0, 2));
        rm1 = fmaxf(rm1, __shfl_xor_sync(0xffffffffu, rm1, 1));
        rm1 = fmaxf(rm1, __shfl_xor_sync(0xffffffffu, rm1, 2));

        const float mn0 = fmaxf(m_i[0], rm0), mn1 = fmaxf(m_i[1], rm1);
        const float sc0 = __expf(m_i[0] - mn0), sc1 = __expf(m_i[1] - mn1);
        l_i[0] *= sc0; l_i[1] *= sc1;

        float rs0 = 0.0f, rs1 = 0.0f;
        #pragma unroll
        for (int j = 0; j < 8; j++) {
            O[j][0] *= sc0; O[j][1] *= sc0; O[j][2] *= sc1; O[j][3] *= sc1;
            S[j][0] = __expf(S[j][0] - mn0); rs0 += S[j][0];
            S[j][1] = __expf(S[j][1] - mn0); rs0 += S[j][1];
            S[j][2] = __expf(S[j][2] - mn1); rs1 += S[j][2];
            S[j][3] = __expf(S[j][3] - mn1); rs1 += S[j][3];
        }
        rs0 += __shfl_xor_sync(0xffffffffu, rs0, 1);
        rs0 += __shfl_xor_sync(0xffffffffu, rs0, 2);
        rs1 += __shfl_xor_sync(0xffffffffu, rs1, 1);
        rs1 += __shfl_xor_sync(0xffffffffu, rs1, 2);
        l_i[0] += rs0; l_i[1] += rs1;
        m_i[0] = mn0;  m_i[1] = mn1;

        // P -> smem (tf32); warp-private rows, so only __syncwarp needed
        #pragma unroll
        for (int j = 0; j < 8; j++) {
            const int cc = j*8 + 2*tg;
            Ps[(r0 + g    )*AST + cc    ] = f2tf(S[j][0]);
            Ps[(r0 + g    )*AST + cc + 1] = f2tf(S[j][1]);
            Ps[(r0 + 8 + g)*AST + cc    ] = f2tf(S[j][2]);
            Ps[(r0 + 8 + g)*AST + cc + 1] = f2tf(S[j][3]);
        }
        __syncwarp();

        // O += P V
        #pragma unroll
        for (int ks = 0; ks < 8; ks++) {
            const int kk = ks*8;
            const int ar = (r0 + g)*AST + kk + tg;
            uint32_t a0 = Ps[ar],     a1 = Ps[ar + 8*AST];
            uint32_t a2 = Ps[ar + 4], a3 = Ps[ar + 8*AST + 4];
            #pragma unroll
            for (int j = 0; j < 8; j++) {
                const int nb = j*8 + g;
                mma8(O[j], a0,a1,a2,a3,
                     Vs[(kk + tg)*AST + nb], Vs[(kk + tg + 4)*AST + nb]);
            }
        }
        __syncwarp();   // protect Ps before next iteration's overwrite
    }

    // normalize + store to g_vals [B,S,E], E index = h*64 + d
    const int b = bh >> 4, h = bh & 15;
    const float inv0 = 1.0f / l_i[0], inv1 = 1.0f / l_i[1];
    const int q0 = jq*BQ + r0 + g, q1 = q0 + 8;
    const size_t base0 = ((size_t)(b*Sc + q0))*Ec + h*HDc;
    const size_t base1 = ((size_t)(b*Sc + q1))*Ec + h*HDc;
    #pragma unroll
    for (int j = 0; j < 8; j++) {
        const int c = j*8 + 2*tg;
        *reinterpret_cast<float2*>(&g_vals[base0 + c]) =
            make_float2(O[j][0]*inv0, O[j][1]*inv0);
        *reinterpret_cast<float2*>(&g_vals[base1 + c]) =
            make_float2(O[j][2]*inv1, O[j][3]*inv1);
    }
}

// ---------------------------------------------------------------------------
extern "C" void kernel_launch(void* const* d_in, const int* in_sizes, int n_in,
                              void* d_out, int out_size)
{
    const float* x    = (const float*)d_in[0];
    const float* Wqkv = (const float*)d_in[1];
    const float* bqkv = (const float*)d_in[2];
    const float* Wout = (const float*)d_in[3];
    const float* bout = (const float*)d_in[4];
    float* out = (float*)d_out;

    float* valsp = nullptr;
    cudaGetSymbolAddress((void**)&valsp, g_vals);

    // 1) QKV projection (split-tf32, fp32-grade) -> scatter into g_q/g_k/g_v
    const int smem_qkv = 4 * 128 * GSK * (int)sizeof(uint32_t);   // 73,728 B
    cudaFuncSetAttribute(gemm_tf32<0, true>,
                         cudaFuncAttributeMaxDynamicSharedMemorySize, smem_qkv);
    gemm_tf32<0, true><<<dim3(Mrows/128, (3*Ec)/128), 256, smem_qkv>>>(
        x, Wqkv, bqkv, nullptr, Ec, 3*Ec);

    // 2) Attention -> g_vals [B,S,E]
    const int smem_attn = (BQ + TK + TK + BQ) * AST * (int)sizeof(uint32_t); // 104,448 B
    cudaFuncSetAttribute(attn_tf32,
                         cudaFuncAttributeMaxDynamicSharedMemorySize, smem_attn);
    attn_tf32<<<dim3(Sc/BQ, Bc*Hc), 256, smem_attn>>>();

    // 3) Output projection (plain tf32) -> d_out
    const int smem_out = 2 * 128 * GSK * (int)sizeof(uint32_t);   // 36,864 B
    gemm_tf32<1, false><<<dim3(Mrows/128, Ec/128), 256, smem_out>>>(
        valsp, Wout, bout, out, Ec, Ec);
}

// round 10
// speedup vs baseline: 2.3549x; 1.2076x over previous
#include <cuda_runtime.h>
#include <cuda_bf16.h>
#include <math.h>
#include <stdint.h>

// Problem constants
#define Bc   2
#define Sc   2048
#define Ec   1024
#define Hc   16
#define HDc  64
#define Mrows (Bc*Sc)          // 4096
#define NEGBIG (-1.0e9f)

// Scratch (device globals; no allocation allowed)
__device__ float g_q[Bc*Hc*Sc*HDc];     // [B,H,S,HD]
__device__ float g_k[Bc*Hc*Sc*HDc];
__device__ float g_v[Bc*Hc*Sc*HDc];
__device__ float g_vals[Mrows*Ec];      // [B,S,E]

// ---------------------------------------------------------------------------
// mma.sync helpers
// ---------------------------------------------------------------------------
__device__ __forceinline__ uint32_t f2tf(float x) {
    uint32_t r;
    asm("cvt.rna.tf32.f32 %0, %1;" : "=r"(r) : "f"(x));
    return r;
}
__device__ __forceinline__ void mma8(float* c,
    uint32_t a0, uint32_t a1, uint32_t a2, uint32_t a3,
    uint32_t b0, uint32_t b1)
{
    asm volatile(
        "mma.sync.aligned.m16n8k8.row.col.f32.tf32.tf32.f32 "
        "{%0,%1,%2,%3},{%4,%5,%6,%7},{%8,%9},{%0,%1,%2,%3};"
        : "+f"(c[0]), "+f"(c[1]), "+f"(c[2]), "+f"(c[3])
        : "r"(a0), "r"(a1), "r"(a2), "r"(a3), "r"(b0), "r"(b1));
}
__device__ __forceinline__ void mma16(float* c,
    uint32_t a0, uint32_t a1, uint32_t a2, uint32_t a3,
    uint32_t b0, uint32_t b1)
{
    asm volatile(
        "mma.sync.aligned.m16n8k16.row.col.f32.bf16.bf16.f32 "
        "{%0,%1,%2,%3},{%4,%5,%6,%7},{%8,%9},{%0,%1,%2,%3};"
        : "+f"(c[0]), "+f"(c[1]), "+f"(c[2]), "+f"(c[3])
        : "r"(a0), "r"(a1), "r"(a2), "r"(a3), "r"(b0), "r"(b1));
}

// bf16 2-term split of a float pair, packed as bf16x2 words (lo-val in low half)
__device__ __forceinline__ void split2(float x, float y, uint32_t& hi, uint32_t& lo) {
    __nv_bfloat16 hx = __float2bfloat16(x);
    __nv_bfloat16 hy = __float2bfloat16(y);
    __nv_bfloat16 lx = __float2bfloat16(x - __bfloat162float(hx));
    __nv_bfloat16 ly = __float2bfloat16(y - __bfloat162float(hy));
    hi = ((uint32_t)__bfloat16_as_ushort(hy) << 16) | (uint32_t)__bfloat16_as_ushort(hx);
    lo = ((uint32_t)__bfloat16_as_ushort(ly) << 16) | (uint32_t)__bfloat16_as_ushort(lx);
}

// ===========================================================================
// QKV GEMM, split-bf16 m16n8k16: C[m][n] = sum_k A[m][k]*W[n][k] + bias[n]
// Block 128x128, K-chunk 32, 256 threads (8 warps 2x4), warp tile 64x32.
// smem holds bf16x2 words, word-row-stride 18 (even -> uint2-aligned;
// 18g+tg mod 32 distinct for g=0..7 -> conflict-free frag loads).
// 3 MMAs per K=16 (hi*hi + hi*lo + lo*hi) -> fp32-grade accuracy.
// Epilogue scatters into g_q/g_k/g_v per the qkv reshape/transpose/split.
// ===========================================================================
#define SKW 18

__global__ __launch_bounds__(256, 2) void gemm_qkv_bf16(
    const float* __restrict__ A, const float* __restrict__ W,
    const float* __restrict__ bias)
{
    __shared__ uint32_t Ah[128*SKW], Al[128*SKW], Wh[128*SKW], Wl[128*SKW];

    const int tid  = threadIdx.x;
    const int lane = tid & 31, w = tid >> 5;
    const int g = lane >> 2, tg = lane & 3;
    const int wm = w & 1, wn = w >> 1;
    const int m0 = blockIdx.x << 7, n0 = blockIdx.y << 7;
    const int Kdim = Ec;

    float acc[4][4][4];
    #pragma unroll
    for (int i = 0; i < 4; i++)
        #pragma unroll
        for (int j = 0; j < 4; j++)
            #pragma unroll
            for (int r = 0; r < 4; r++) acc[i][j][r] = 0.0f;

    const int lrow = tid >> 1;              // 0..127
    const int lhalf = tid & 1;              // which 16-float half of the 32-chunk
    const float* Aptr = A + (size_t)(m0 + lrow) * Kdim + lhalf * 16;
    const float* Wptr = W + (size_t)(n0 + lrow) * Kdim + lhalf * 16;
    const int wbase = lrow * SKW + lhalf * 8;

    for (int c = 0; c < Kdim / 32; c++) {
        #pragma unroll
        for (int i = 0; i < 4; i++) {
            float4 av = *reinterpret_cast<const float4*>(Aptr + c * 32 + i * 4);
            uint32_t h0, l0, h1, l1;
            split2(av.x, av.y, h0, l0);
            split2(av.z, av.w, h1, l1);
            *reinterpret_cast<uint2*>(&Ah[wbase + 2*i]) = make_uint2(h0, h1);
            *reinterpret_cast<uint2*>(&Al[wbase + 2*i]) = make_uint2(l0, l1);
            float4 wv = *reinterpret_cast<const float4*>(Wptr + c * 32 + i * 4);
            split2(wv.x, wv.y, h0, l0);
            split2(wv.z, wv.w, h1, l1);
            *reinterpret_cast<uint2*>(&Wh[wbase + 2*i]) = make_uint2(h0, h1);
            *reinterpret_cast<uint2*>(&Wl[wbase + 2*i]) = make_uint2(l0, l1);
        }
        __syncthreads();

        #pragma unroll
        for (int step = 0; step < 2; step++) {
            const int kw = step * 8;
            uint32_t bh[4][2], bl[4][2];
            #pragma unroll
            for (int j = 0; j < 4; j++) {
                const int br = (wn*32 + j*8 + g)*SKW + kw + tg;
                bh[j][0] = Wh[br]; bh[j][1] = Wh[br + 4];
                bl[j][0] = Wl[br]; bl[j][1] = Wl[br + 4];
            }
            #pragma unroll
            for (int i = 0; i < 4; i++) {
                const int ar = (wm*64 + i*16 + g)*SKW + kw + tg;
                uint32_t ah0 = Ah[ar],     ah1 = Ah[ar + 8*SKW];
                uint32_t ah2 = Ah[ar + 4], ah3 = Ah[ar + 8*SKW + 4];
                uint32_t al0 = Al[ar],     al1 = Al[ar + 8*SKW];
                uint32_t al2 = Al[ar + 4], al3 = Al[ar + 8*SKW + 4];
                #pragma unroll
                for (int j = 0; j < 4; j++) {
                    mma16(acc[i][j], ah0,ah1,ah2,ah3, bh[j][0], bh[j][1]);
                    mma16(acc[i][j], ah0,ah1,ah2,ah3, bl[j][0], bl[j][1]);
                    mma16(acc[i][j], al0,al1,al2,al3, bh[j][0], bh[j][1]);
                }
            }
        }
        __syncthreads();
    }

    // Epilogue: C layout identical to m16n8k8 (c0 (g,2tg) c1 (g,2tg+1) c2/c3 +8 rows)
    #pragma unroll
    for (int i = 0; i < 4; i++) {
        const int mlo = m0 + wm*64 + i*16 + g;
        #pragma unroll
        for (int j = 0; j < 4; j++) {
            const int n = n0 + wn*32 + j*8 + 2*tg;
            const float b0 = __ldg(&bias[n]), b1 = __ldg(&bias[n+1]);
            #pragma unroll
            for (int half = 0; half < 2; half++) {
                const int m = mlo + half*8;
                const float v0 = acc[i][j][half*2+0] + b0;
                const float v1 = acc[i][j][half*2+1] + b1;
                const int h = n / 192, r = n - h*192;
                const int part = r >> 6, d = r & 63;
                const int b = m >> 11, s = m & 2047;
                float* dst = (part == 0) ? g_q : (part == 1) ? g_k : g_v;
                *reinterpret_cast<float2*>(&dst[(((b*Hc + h)*Sc) + s)*HDc + d]) =
                    make_float2(v0, v1);
            }
        }
    }
}

// ===========================================================================
// Output-projection GEMM, plain tf32 (round-5 verified math), static smem,
// launch_bounds(256,2) for 2 CTAs/SM.
// ===========================================================================
#define GSK 36

__global__ __launch_bounds__(256, 2) void gemm_out_tf32(
    const float* __restrict__ A, const float* __restrict__ W,
    const float* __restrict__ bias, float* __restrict__ Cplain)
{
    __shared__ uint32_t Ah[128*GSK], Wh[128*GSK];

    const int tid  = threadIdx.x;
    const int lane = tid & 31, w = tid >> 5;
    const int g = lane >> 2, tg = lane & 3;
    const int wm = w & 1, wn = w >> 1;
    const int m0 = blockIdx.x << 7, n0 = blockIdx.y << 7;
    const int Kdim = Ec, Ncols = Ec;

    float acc[4][4][4];
    #pragma unroll
    for (int i = 0; i < 4; i++)
        #pragma unroll
        for (int j = 0; j < 4; j++)
            #pragma unroll
            for (int r = 0; r < 4; r++) acc[i][j][r] = 0.0f;

    const int lr = tid >> 3;
    const int lc = (tid & 7) << 2;

    for (int k0 = 0; k0 < Kdim; k0 += 32) {
        #pragma unroll
        for (int p = 0; p < 4; p++) {
            const int row = lr + p*32;
            float4 av = *reinterpret_cast<const float4*>(A + (size_t)(m0+row)*Kdim + k0 + lc);
            float4 wv = *reinterpret_cast<const float4*>(W + (size_t)(n0+row)*Kdim + k0 + lc);
            *reinterpret_cast<uint4*>(&Ah[row*GSK + lc]) =
                make_uint4(f2tf(av.x), f2tf(av.y), f2tf(av.z), f2tf(av.w));
            *reinterpret_cast<uint4*>(&Wh[row*GSK + lc]) =
                make_uint4(f2tf(wv.x), f2tf(wv.y), f2tf(wv.z), f2tf(wv.w));
        }
        __syncthreads();

        #pragma unroll
        for (int ks = 0; ks < 4; ks++) {
            const int kk = ks*8;
            uint32_t bh[4][2];
            #pragma unroll
            for (int j = 0; j < 4; j++) {
                const int n = (wn*32 + j*8 + g)*GSK + kk + tg;
                bh[j][0] = Wh[n]; bh[j][1] = Wh[n+4];
            }
            #pragma unroll
            for (int i = 0; i < 4; i++) {
                const int mr = (wm*64 + i*16 + g)*GSK + kk + tg;
                uint32_t a0 = Ah[mr],     a1 = Ah[mr + 8*GSK];
                uint32_t a2 = Ah[mr + 4], a3 = Ah[mr + 8*GSK + 4];
                #pragma unroll
                for (int j = 0; j < 4; j++)
                    mma8(acc[i][j], a0,a1,a2,a3, bh[j][0], bh[j][1]);
            }
        }
        __syncthreads();
    }

    #pragma unroll
    for (int i = 0; i < 4; i++) {
        const int mlo = m0 + wm*64 + i*16 + g;
        #pragma unroll
        for (int j = 0; j < 4; j++) {
            const int n = n0 + wn*32 + j*8 + 2*tg;
            const float b0 = __ldg(&bias[n]), b1 = __ldg(&bias[n+1]);
            #pragma unroll
            for (int half = 0; half < 2; half++) {
                const int m = mlo + half*8;
                *reinterpret_cast<float2*>(&Cplain[(size_t)m*Ncols + n]) =
                    make_float2(acc[i][j][half*2+0] + b0,
                                acc[i][j][half*2+1] + b1);
            }
        }
    }
}

// ---------------------------------------------------------------------------
// Flash attention, tf32 mma.sync (unchanged from round 5; verified).
// ---------------------------------------------------------------------------
#define AST 68
#define BQ  128
#define TK  64

__global__ __launch_bounds__(256) void attn_tf32()
{
    extern __shared__ uint32_t sm[];
    uint32_t* Qs = sm;                  // BQ*AST
    uint32_t* Ks = Qs + BQ*AST;         // TK*AST
    uint32_t* Vs = Ks + TK*AST;         // TK*AST
    uint32_t* Ps = Vs + TK*AST;         // BQ*AST

    const int tid  = threadIdx.x;
    const int lane = tid & 31, w = tid >> 5;
    const int g = lane >> 2, tg = lane & 3;
    const int jq = blockIdx.x;
    const int bh = blockIdx.y;

    const float* Qg = g_q + (size_t)bh * Sc * HDc;
    const float* Kg = g_k + (size_t)bh * Sc * HDc;
    const float* Vg = g_v + (size_t)bh * Sc * HDc;

    #pragma unroll
    for (int p = 0; p < 8; p++) {
        const int idx = tid + p*256;
        const int r = idx >> 4, c = (idx & 15) << 2;
        float4 v = *reinterpret_cast<const float4*>(Qg + (size_t)(jq*BQ + r)*HDc + c);
        *reinterpret_cast<uint4*>(&Qs[r*AST + c]) =
            make_uint4(f2tf(v.x), f2tf(v.y), f2tf(v.z), f2tf(v.w));
    }

    float m_i[2] = {-INFINITY, -INFINITY};
    float l_i[2] = {0.0f, 0.0f};
    float O[8][4];
    #pragma unroll
    for (int j = 0; j < 8; j++)
        #pragma unroll
        for (int r = 0; r < 4; r++) O[j][r] = 0.0f;

    const int r0 = w * 16;
    const int kstart = (jq == (Sc/BQ - 1)) ? 0 : 2*jq;

    for (int jk = kstart; jk < Sc/TK; jk++) {
        __syncthreads();
        #pragma unroll
        for (int p = 0; p < 4; p++) {
            const int idx = tid + p*256;
            const int r = idx >> 4, c = (idx & 15) << 2;
            float4 kv = *reinterpret_cast<const float4*>(Kg + (size_t)(jk*TK + r)*HDc + c);
            float4 vv = *reinterpret_cast<const float4*>(Vg + (size_t)(jk*TK + r)*HDc + c);
            *reinterpret_cast<uint4*>(&Ks[r*AST + c]) =
                make_uint4(f2tf(kv.x), f2tf(kv.y), f2tf(kv.z), f2tf(kv.w));
            *reinterpret_cast<uint4*>(&Vs[r*AST + c]) =
                make_uint4(f2tf(vv.x), f2tf(vv.y), f2tf(vv.z), f2tf(vv.w));
        }
        __syncthreads();

        float S[8][4];
        #pragma unroll
        for (int j = 0; j < 8; j++)
            #pragma unroll
            for (int r = 0; r < 4; r++) S[j][r] = 0.0f;

        #pragma unroll
        for (int ks = 0; ks < 8; ks++) {
            const int kk = ks*8;
            const int ar = (r0 + g)*AST + kk + tg;
            uint32_t a0 = Qs[ar],     a1 = Qs[ar + 8*AST];
            uint32_t a2 = Qs[ar + 4], a3 = Qs[ar + 8*AST + 4];
            #pragma unroll
            for (int j = 0; j < 8; j++) {
                const int br = (j*8 + g)*AST + kk + tg;
                mma8(S[j], a0,a1,a2,a3, Ks[br], Ks[br + 4]);
            }
        }

        const int qlo = jq*BQ + r0 + g, qhi = qlo + 8;
        #pragma unroll
        for (int j = 0; j < 8; j++) {
            const int c0 = jk*TK + j*8 + 2*tg;
            S[j][0] = S[j][0]*0.125f + ((c0    ) <= qlo ? NEGBIG : 0.0f);
            S[j][1] = S[j][1]*0.125f + ((c0 + 1) <= qlo ? NEGBIG : 0.0f);
            S[j][2] = S[j][2]*0.125f + ((c0    ) <= qhi ? NEGBIG : 0.0f);
            S[j][3] = S[j][3]*0.125f + ((c0 + 1) <= qhi ? NEGBIG : 0.0f);
        }

        float rm0 = -INFINITY, rm1 = -INFINITY;
        #pragma unroll
        for (int j = 0; j < 8; j++) {
            rm0 = fmaxf(rm0, fmaxf(S[j][0], S[j][1]));
            rm1 = fmaxf(rm1, fmaxf(S[j][2], S[j][3]));
        }
        rm0 = fmaxf(rm0, __shfl_xor_sync(0xffffffffu, rm0, 1));
        rm0 = fmaxf(rm0, __shfl_xor_sync(0xffffffffu, rm0, 2));
        rm1 = fmaxf(rm1, __shfl_xor_sync(0xffffffffu, rm1, 1));
        rm1 = fmaxf(rm1, __shfl_xor_sync(0xffffffffu, rm1, 2));

        const float mn0 = fmaxf(m_i[0], rm0), mn1 = fmaxf(m_i[1], rm1);
        const float sc0 = __expf(m_i[0] - mn0), sc1 = __expf(m_i[1] - mn1);
        l_i[0] *= sc0; l_i[1] *= sc1;

        float rs0 = 0.0f, rs1 = 0.0f;
        #pragma unroll
        for (int j = 0; j < 8; j++) {
            O[j][0] *= sc0; O[j][1] *= sc0; O[j][2] *= sc1; O[j][3] *= sc1;
            S[j][0] = __expf(S[j][0] - mn0); rs0 += S[j][0];
            S[j][1] = __expf(S[j][1] - mn0); rs0 += S[j][1];
            S[j][2] = __expf(S[j][2] - mn1); rs1 += S[j][2];
            S[j][3] = __expf(S[j][3] - mn1); rs1 += S[j][3];
        }
        rs0 += __shfl_xor_sync(0xffffffffu, rs0, 1);
        rs0 += __shfl_xor_sync(0xffffffffu, rs0, 2);
        rs1 += __shfl_xor_sync(0xffffffffu, rs1, 1);
        rs1 += __shfl_xor_sync(0xffffffffu, rs1, 2);
        l_i[0] += rs0; l_i[1] += rs1;
        m_i[0] = mn0;  m_i[1] = mn1;

        #pragma unroll
        for (int j = 0; j < 8; j++) {
            const int cc = j*8 + 2*tg;
            Ps[(r0 + g    )*AST + cc    ] = f2tf(S[j][0]);
            Ps[(r0 + g    )*AST + cc + 1] = f2tf(S[j][1]);
            Ps[(r0 + 8 + g)*AST + cc    ] = f2tf(S[j][2]);
            Ps[(r0 + 8 + g)*AST + cc + 1] = f2tf(S[j][3]);
        }
        __syncwarp();

        #pragma unroll
        for (int ks = 0; ks < 8; ks++) {
            const int kk = ks*8;
            const int ar = (r0 + g)*AST + kk + tg;
            uint32_t a0 = Ps[ar],     a1 = Ps[ar + 8*AST];
            uint32_t a2 = Ps[ar + 4], a3 = Ps[ar + 8*AST + 4];
            #pragma unroll
            for (int j = 0; j < 8; j++) {
                const int nb = j*8 + g;
                mma8(O[j], a0,a1,a2,a3,
                     Vs[(kk + tg)*AST + nb], Vs[(kk + tg + 4)*AST + nb]);
            }
        }
        __syncwarp();
    }

    const int b = bh >> 4, h = bh & 15;
    const float inv0 = 1.0f / l_i[0], inv1 = 1.0f / l_i[1];
    const int q0 = jq*BQ + r0 + g, q1 = q0 + 8;
    const size_t base0 = ((size_t)(b*Sc + q0))*Ec + h*HDc;
    const size_t base1 = ((size_t)(b*Sc + q1))*Ec + h*HDc;
    #pragma unroll
    for (int j = 0; j < 8; j++) {
        const int c = j*8 + 2*tg;
        *reinterpret_cast<float2*>(&g_vals[base0 + c]) =
            make_float2(O[j][0]*inv0, O[j][1]*inv0);
        *reinterpret_cast<float2*>(&g_vals[base1 + c]) =
            make_float2(O[j][2]*inv1, O[j][3]*inv1);
    }
}

// ---------------------------------------------------------------------------
extern "C" void kernel_launch(void* const* d_in, const int* in_sizes, int n_in,
                              void* d_out, int out_size)
{
    const float* x    = (const float*)d_in[0];
    const float* Wqkv = (const float*)d_in[1];
    const float* bqkv = (const float*)d_in[2];
    const float* Wout = (const float*)d_in[3];
    const float* bout = (const float*)d_in[4];
    float* out = (float*)d_out;

    float* valsp = nullptr;
    cudaGetSymbolAddress((void**)&valsp, g_vals);

    // 1) QKV projection (split-bf16 m16n8k16) -> scatter into g_q/g_k/g_v
    gemm_qkv_bf16<<<dim3(Mrows/128, (3*Ec)/128), 256>>>(x, Wqkv, bqkv);

    // 2) Attention -> g_vals [B,S,E]
    const int smem_attn = (BQ + TK + TK + BQ) * AST * (int)sizeof(uint32_t);
    cudaFuncSetAttribute(attn_tf32,
                         cudaFuncAttributeMaxDynamicSharedMemorySize, smem_attn);
    attn_tf32<<<dim3(Sc/BQ, Bc*Hc), 256, smem_attn>>>();

    // 3) Output projection (plain tf32) -> d_out
    gemm_out_tf32<<<dim3(Mrows/128, Ec/128), 256>>>(valsp, Wout, bout, out);
}

// round 12
// speedup vs baseline: 3.2471x; 1.3789x over previous
#include <cuda_runtime.h>
#include <cuda_bf16.h>
#include <math.h>
#include <stdint.h>

// Problem constants
#define Bc   2
#define Sc   2048
#define Ec   1024
#define Hc   16
#define HDc  64
#define Mrows (Bc*Sc)          // 4096
#define NEGBIG (-1.0e9f)

// Scratch (device globals; no allocation allowed)
__device__ float g_q[Bc*Hc*Sc*HDc];     // [B,H,S,HD]
__device__ float g_k[Bc*Hc*Sc*HDc];
__device__ float g_v[Bc*Hc*Sc*HDc];
__device__ float g_vals[Mrows*Ec];      // [B,S,E]

// ---------------------------------------------------------------------------
// mma.sync helpers
// ---------------------------------------------------------------------------
__device__ __forceinline__ uint32_t f2tf(float x) {
    uint32_t r;
    asm("cvt.rna.tf32.f32 %0, %1;" : "=r"(r) : "f"(x));
    return r;
}
__device__ __forceinline__ void mma8(float* c,
    uint32_t a0, uint32_t a1, uint32_t a2, uint32_t a3,
    uint32_t b0, uint32_t b1)
{
    asm volatile(
        "mma.sync.aligned.m16n8k8.row.col.f32.tf32.tf32.f32 "
        "{%0,%1,%2,%3},{%4,%5,%6,%7},{%8,%9},{%0,%1,%2,%3};"
        : "+f"(c[0]), "+f"(c[1]), "+f"(c[2]), "+f"(c[3])
        : "r"(a0), "r"(a1), "r"(a2), "r"(a3), "r"(b0), "r"(b1));
}

// ===========================================================================
// Unified plain-tf32 GEMM: C[m][n] = sum_k A[m][k]*W[n][k] + bias[n]
// Block tile 128(M) x 256(N), K-chunk 32, 256 threads = 8 warps (2m x 4n),
// warp tile 64x64 (i<4 m-frags, j<8 n-frags) -> 128 B of smem frag traffic
// per MMA (vs 192 at 64x32). Double-buffered smem + register-staged gmem
// prefetch of the next K-chunk overlaps LDG latency with the MMA loop.
// smem word-stride 36: frag-load banks (4g+tg) mod 32 distinct -> conflict-
// free; 36 words = 144B (16B mult) -> aligned uint4 stores, conflict-free.
// MODE 0: scatter epilogue into g_q/g_k/g_v; MODE 1: plain row-major store.
// ===========================================================================
#define ST   36
#define BUFW (384*ST)                 // words per buffer (128 A-rows + 256 W-rows)
#define G2_SMEM (2*BUFW*4)            // 110,592 B

__device__ __forceinline__ void ld_chunk(const float* Ap, const float* Wp,
                                         int Kd, int koff,
                                         float4* ra, float4* rw)
{
    #pragma unroll
    for (int p = 0; p < 4; p++)
        ra[p] = *reinterpret_cast<const float4*>(Ap + (size_t)p*32*Kd + koff);
    #pragma unroll
    for (int p = 0; p < 8; p++)
        rw[p] = *reinterpret_cast<const float4*>(Wp + (size_t)p*32*Kd + koff);
}
__device__ __forceinline__ void st_chunk(uint32_t* As, uint32_t* Ws, int wbase,
                                         const float4* ra, const float4* rw)
{
    #pragma unroll
    for (int p = 0; p < 4; p++)
        *reinterpret_cast<uint4*>(&As[wbase + p*32*ST]) =
            make_uint4(f2tf(ra[p].x), f2tf(ra[p].y), f2tf(ra[p].z), f2tf(ra[p].w));
    #pragma unroll
    for (int p = 0; p < 8; p++)
        *reinterpret_cast<uint4*>(&Ws[wbase + p*32*ST]) =
            make_uint4(f2tf(rw[p].x), f2tf(rw[p].y), f2tf(rw[p].z), f2tf(rw[p].w));
}

template<int MODE>
__global__ __launch_bounds__(256, 1) void gemm2_tf32(
    const float* __restrict__ A, const float* __restrict__ W,
    const float* __restrict__ bias, float* __restrict__ Cplain, int Ncols)
{
    extern __shared__ uint32_t sh[];

    const int tid  = threadIdx.x;
    const int lane = tid & 31, w = tid >> 5;
    const int g = lane >> 2, tg = lane & 3;
    const int wm = w & 1, wn = w >> 1;            // 2 x 4 warp grid
    const int m0 = blockIdx.x << 7, n0 = blockIdx.y << 8;
    const int Kdim = Ec;

    float acc[4][8][4];
    #pragma unroll
    for (int i = 0; i < 4; i++)
        #pragma unroll
        for (int j = 0; j < 8; j++)
            #pragma unroll
            for (int r = 0; r < 4; r++) acc[i][j][r] = 0.0f;

    const int lr = tid >> 3;             // 0..31
    const int lc = (tid & 7) << 2;       // 0..28
    const float* Ap = A + (size_t)(m0 + lr) * Kdim + lc;
    const float* Wp = W + (size_t)(n0 + lr) * Kdim + lc;
    const int wbase = lr * ST + lc;

    float4 ra[4], rw[8];
    ld_chunk(Ap, Wp, Kdim, 0, ra, rw);
    st_chunk(sh, sh + 128*ST, wbase, ra, rw);
    __syncthreads();

    const int nch = Kdim / 32;
    for (int c = 0; c < nch; c++) {
        uint32_t* As = sh + (c & 1) * BUFW;
        uint32_t* Ws = As + 128*ST;
        const bool more = (c + 1 < nch);
        if (more) ld_chunk(Ap, Wp, Kdim, (c + 1) * 32, ra, rw);

        #pragma unroll
        for (int ks = 0; ks < 4; ks++) {
            const int kk = ks * 8;
            uint32_t bf[8][2];
            #pragma unroll
            for (int j = 0; j < 8; j++) {
                const int br = (wn*64 + j*8 + g)*ST + kk + tg;
                bf[j][0] = Ws[br]; bf[j][1] = Ws[br + 4];
            }
            #pragma unroll
            for (int i = 0; i < 4; i++) {
                const int ar = (wm*64 + i*16 + g)*ST + kk + tg;
                uint32_t a0 = As[ar],     a1 = As[ar + 8*ST];
                uint32_t a2 = As[ar + 4], a3 = As[ar + 8*ST + 4];
                #pragma unroll
                for (int j = 0; j < 8; j++)
                    mma8(acc[i][j], a0, a1, a2, a3, bf[j][0], bf[j][1]);
            }
        }

        if (more) {
            uint32_t* Asn = sh + ((c + 1) & 1) * BUFW;
            st_chunk(Asn, Asn + 128*ST, wbase, ra, rw);
            __syncthreads();
        }
    }

    // Epilogue: c0 (g,2tg) c1 (g,2tg+1) c2 (g+8,2tg) c3 (g+8,2tg+1)
    #pragma unroll
    for (int i = 0; i < 4; i++) {
        const int mlo = m0 + wm*64 + i*16 + g;
        #pragma unroll
        for (int j = 0; j < 8; j++) {
            const int n = n0 + wn*64 + j*8 + 2*tg;
            const float b0 = __ldg(&bias[n]), b1 = __ldg(&bias[n+1]);
            #pragma unroll
            for (int half = 0; half < 2; half++) {
                const int m = mlo + half*8;
                const float v0 = acc[i][j][half*2+0] + b0;
                const float v1 = acc[i][j][half*2+1] + b1;
                if (MODE == 0) {
                    const int h = n / 192, r = n - h*192;
                    const int part = r >> 6, d = r & 63;
                    const int b = m >> 11, s = m & 2047;
                    float* dst = (part == 0) ? g_q : (part == 1) ? g_k : g_v;
                    *reinterpret_cast<float2*>(&dst[(((b*Hc + h)*Sc) + s)*HDc + d]) =
                        make_float2(v0, v1);
                } else {
                    *reinterpret_cast<float2*>(&Cplain[(size_t)m*Ncols + n]) =
                        make_float2(v0, v1);
                }
            }
        }
    }
}

// ---------------------------------------------------------------------------
// Flash attention, tf32 mma.sync (unchanged from round 5; verified).
// ---------------------------------------------------------------------------
#define AST 68
#define BQ  128
#define TK  64

__global__ __launch_bounds__(256) void attn_tf32()
{
    extern __shared__ uint32_t sm[];
    uint32_t* Qs = sm;                  // BQ*AST
    uint32_t* Ks = Qs + BQ*AST;         // TK*AST
    uint32_t* Vs = Ks + TK*AST;         // TK*AST
    uint32_t* Ps = Vs + TK*AST;         // BQ*AST

    const int tid  = threadIdx.x;
    const int lane = tid & 31, w = tid >> 5;
    const int g = lane >> 2, tg = lane & 3;
    const int jq = blockIdx.x;
    const int bh = blockIdx.y;

    const float* Qg = g_q + (size_t)bh * Sc * HDc;
    const float* Kg = g_k + (size_t)bh * Sc * HDc;
    const float* Vg = g_v + (size_t)bh * Sc * HDc;

    #pragma unroll
    for (int p = 0; p < 8; p++) {
        const int idx = tid + p*256;
        const int r = idx >> 4, c = (idx & 15) << 2;
        float4 v = *reinterpret_cast<const float4*>(Qg + (size_t)(jq*BQ + r)*HDc + c);
        *reinterpret_cast<uint4*>(&Qs[r*AST + c]) =
            make_uint4(f2tf(v.x), f2tf(v.y), f2tf(v.z), f2tf(v.w));
    }

    float m_i[2] = {-INFINITY, -INFINITY};
    float l_i[2] = {0.0f, 0.0f};
    float O[8][4];
    #pragma unroll
    for (int j = 0; j < 8; j++)
        #pragma unroll
        for (int r = 0; r < 4; r++) O[j][r] = 0.0f;

    const int r0 = w * 16;
    const int kstart = (jq == (Sc/BQ - 1)) ? 0 : 2*jq;

    for (int jk = kstart; jk < Sc/TK; jk++) {
        __syncthreads();
        #pragma unroll
        for (int p = 0; p < 4; p++) {
            const int idx = tid + p*256;
            const int r = idx >> 4, c = (idx & 15) << 2;
            float4 kv = *reinterpret_cast<const float4*>(Kg + (size_t)(jk*TK + r)*HDc + c);
            float4 vv = *reinterpret_cast<const float4*>(Vg + (size_t)(jk*TK + r)*HDc + c);
            *reinterpret_cast<uint4*>(&Ks[r*AST + c]) =
                make_uint4(f2tf(kv.x), f2tf(kv.y), f2tf(kv.z), f2tf(kv.w));
            *reinterpret_cast<uint4*>(&Vs[r*AST + c]) =
                make_uint4(f2tf(vv.x), f2tf(vv.y), f2tf(vv.z), f2tf(vv.w));
        }
        __syncthreads();

        float S[8][4];
        #pragma unroll
        for (int j = 0; j < 8; j++)
            #pragma unroll
            for (int r = 0; r < 4; r++) S[j][r] = 0.0f;

        #pragma unroll
        for (int ks = 0; ks < 8; ks++) {
            const int kk = ks*8;
            const int ar = (r0 + g)*AST + kk + tg;
            uint32_t a0 = Qs[ar],     a1 = Qs[ar + 8*AST];
            uint32_t a2 = Qs[ar + 4], a3 = Qs[ar + 8*AST + 4];
            #pragma unroll
            for (int j = 0; j < 8; j++) {
                const int br = (j*8 + g)*AST + kk + tg;
                mma8(S[j], a0,a1,a2,a3, Ks[br], Ks[br + 4]);
            }
        }

        const int qlo = jq*BQ + r0 + g, qhi = qlo + 8;
        #pragma unroll
        for (int j = 0; j < 8; j++) {
            const int c0 = jk*TK + j*8 + 2*tg;
            S[j][0] = S[j][0]*0.125f + ((c0    ) <= qlo ? NEGBIG : 0.0f);
            S[j][1] = S[j][1]*0.125f + ((c0 + 1) <= qlo ? NEGBIG : 0.0f);
            S[j][2] = S[j][2]*0.125f + ((c0    ) <= qhi ? NEGBIG : 0.0f);
            S[j][3] = S[j][3]*0.125f + ((c0 + 1) <= qhi ? NEGBIG : 0.0f);
        }

        float rm0 = -INFINITY, rm1 = -INFINITY;
        #pragma unroll
        for (int j = 0; j < 8; j++) {
            rm0 = fmaxf(rm0, fmaxf(S[j][0], S[j][1]));
            rm1 = fmaxf(rm1, fmaxf(S[j][2], S[j][3]));
        }
        rm0 = fmaxf(rm0, __shfl_xor_sync(0xffffffffu, rm0, 1));
        rm0 = fmaxf(rm0, __shfl_xor_sync(0xffffffffu, rm0, 2));
        rm1 = fmaxf(rm1, __shfl_xor_sync(0xffffffffu, rm1, 1));
        rm1 = fmaxf(rm1, __shfl_xor_sync(0xffffffffu, rm1, 2));

        const float mn0 = fmaxf(m_i[0], rm0), mn1 = fmaxf(m_i[1], rm1);
        const float sc0 = __expf(m_i[0] - mn0), sc1 = __expf(m_i[1] - mn1);
        l_i[0] *= sc0; l_i[1] *= sc1;

        float rs0 = 0.0f, rs1 = 0.0f;
        #pragma unroll
        for (int j = 0; j < 8; j++) {
            O[j][0] *= sc0; O[j][1] *= sc0; O[j][2] *= sc1; O[j][3] *= sc1;
            S[j][0] = __expf(S[j][0] - mn0); rs0 += S[j][0];
            S[j][1] = __expf(S[j][1] - mn0); rs0 += S[j][1];
            S[j][2] = __expf(S[j][2] - mn1); rs1 += S[j][2];
            S[j][3] = __expf(S[j][3] - mn1); rs1 += S[j][3];
        }
        rs0 += __shfl_xor_sync(0xffffffffu, rs0, 1);
        rs0 += __shfl_xor_sync(0xffffffffu, rs0, 2);
        rs1 += __shfl_xor_sync(0xffffffffu, rs1, 1);
        rs1 += __shfl_xor_sync(0xffffffffu, rs1, 2);
        l_i[0] += rs0; l_i[1] += rs1;
        m_i[0] = mn0;  m_i[1] = mn1;

        #pragma unroll
        for (int j = 0; j < 8; j++) {
            const int cc = j*8 + 2*tg;
            Ps[(r0 + g    )*AST + cc    ] = f2tf(S[j][0]);
            Ps[(r0 + g    )*AST + cc + 1] = f2tf(S[j][1]);
            Ps[(r0 + 8 + g)*AST + cc    ] = f2tf(S[j][2]);
            Ps[(r0 + 8 + g)*AST + cc + 1] = f2tf(S[j][3]);
        }
        __syncwarp();

        #pragma unroll
        for (int ks = 0; ks < 8; ks++) {
            const int kk = ks*8;
            const int ar = (r0 + g)*AST + kk + tg;
            uint32_t a0 = Ps[ar],     a1 = Ps[ar + 8*AST];
            uint32_t a2 = Ps[ar + 4], a3 = Ps[ar + 8*AST + 4];
            #pragma unroll
            for (int j = 0; j < 8; j++) {
                const int nb = j*8 + g;
                mma8(O[j], a0,a1,a2,a3,
                     Vs[(kk + tg)*AST + nb], Vs[(kk + tg + 4)*AST + nb]);
            }
        }
        __syncwarp();
    }

    const int b = bh >> 4, h = bh & 15;
    const float inv0 = 1.0f / l_i[0], inv1 = 1.0f / l_i[1];
    const int q0 = jq*BQ + r0 + g, q1 = q0 + 8;
    const size_t base0 = ((size_t)(b*Sc + q0))*Ec + h*HDc;
    const size_t base1 = ((size_t)(b*Sc + q1))*Ec + h*HDc;
    #pragma unroll
    for (int j = 0; j < 8; j++) {
        const int c = j*8 + 2*tg;
        *reinterpret_cast<float2*>(&g_vals[base0 + c]) =
            make_float2(O[j][0]*inv0, O[j][1]*inv0);
        *reinterpret_cast<float2*>(&g_vals[base1 + c]) =
            make_float2(O[j][2]*inv1, O[j][3]*inv1);
    }
}

// ---------------------------------------------------------------------------
extern "C" void kernel_launch(void* const* d_in, const int* in_sizes, int n_in,
                              void* d_out, int out_size)
{
    const float* x    = (const float*)d_in[0];
    const float* Wqkv = (const float*)d_in[1];
    const float* bqkv = (const float*)d_in[2];
    const float* Wout = (const float*)d_in[3];
    const float* bout = (const float*)d_in[4];
    float* out = (float*)d_out;

    float* valsp = nullptr;
    cudaGetSymbolAddress((void**)&valsp, g_vals);

    cudaFuncSetAttribute(gemm2_tf32<0>,
                         cudaFuncAttributeMaxDynamicSharedMemorySize, G2_SMEM);
    cudaFuncSetAttribute(gemm2_tf32<1>,
                         cudaFuncAttributeMaxDynamicSharedMemorySize, G2_SMEM);

    // 1) QKV projection (plain tf32, 128x256 tiles) -> scatter into g_q/g_k/g_v
    gemm2_tf32<0><<<dim3(Mrows/128, (3*Ec)/256), 256, G2_SMEM>>>(
        x, Wqkv, bqkv, nullptr, 0);

    // 2) Attention -> g_vals [B,S,E]
    const int smem_attn = (BQ + TK + TK + BQ) * AST * (int)sizeof(uint32_t);
    cudaFuncSetAttribute(attn_tf32,
                         cudaFuncAttributeMaxDynamicSharedMemorySize, smem_attn);
    attn_tf32<<<dim3(Sc/BQ, Bc*Hc), 256, smem_attn>>>();

    // 3) Output projection (plain tf32) -> d_out
    gemm2_tf32<1><<<dim3(Mrows/128, Ec/256), 256, G2_SMEM>>>(
        valsp, Wout, bout, out, Ec);
}

// round 13
// speedup vs baseline: 3.2834x; 1.0112x over previous
#include <cuda_runtime.h>
#include <cuda_bf16.h>
#include <math.h>
#include <stdint.h>

// Problem constants
#define Bc   2
#define Sc   2048
#define Ec   1024
#define Hc   16
#define HDc  64
#define Mrows (Bc*Sc)          // 4096
#define NEGBIG (-1.0e9f)
#define FULLM 0xffffffffu

// Scratch (device globals; no allocation allowed)
__device__ float g_q[Bc*Hc*Sc*HDc];     // [B,H,S,HD]
__device__ float g_k[Bc*Hc*Sc*HDc];
__device__ float g_v[Bc*Hc*Sc*HDc];
__device__ float g_vals[Mrows*Ec];      // [B,S,E]

// ---------------------------------------------------------------------------
// mma.sync helpers
// ---------------------------------------------------------------------------
__device__ __forceinline__ uint32_t f2tf(float x) {
    uint32_t r;
    asm("cvt.rna.tf32.f32 %0, %1;" : "=r"(r) : "f"(x));
    return r;
}
__device__ __forceinline__ void mma8(float* c,
    uint32_t a0, uint32_t a1, uint32_t a2, uint32_t a3,
    uint32_t b0, uint32_t b1)
{
    asm volatile(
        "mma.sync.aligned.m16n8k8.row.col.f32.tf32.tf32.f32 "
        "{%0,%1,%2,%3},{%4,%5,%6,%7},{%8,%9},{%0,%1,%2,%3};"
        : "+f"(c[0]), "+f"(c[1]), "+f"(c[2]), "+f"(c[3])
        : "r"(a0), "r"(a1), "r"(a2), "r"(a3), "r"(b0), "r"(b1));
}

// ===========================================================================
// Unified plain-tf32 GEMM (unchanged from round 12; verified).
// Block tile 128(M) x 256(N), K-chunk 32, 8 warps, warp tile 64x64,
// double-buffered smem + register-staged gmem prefetch.
// MODE 0: scatter epilogue into g_q/g_k/g_v; MODE 1: plain row-major store.
// ===========================================================================
#define ST   36
#define BUFW (384*ST)
#define G2_SMEM (2*BUFW*4)

__device__ __forceinline__ void ld_chunk(const float* Ap, const float* Wp,
                                         int Kd, int koff,
                                         float4* ra, float4* rw)
{
    #pragma unroll
    for (int p = 0; p < 4; p++)
        ra[p] = *reinterpret_cast<const float4*>(Ap + (size_t)p*32*Kd + koff);
    #pragma unroll
    for (int p = 0; p < 8; p++)
        rw[p] = *reinterpret_cast<const float4*>(Wp + (size_t)p*32*Kd + koff);
}
__device__ __forceinline__ void st_chunk(uint32_t* As, uint32_t* Ws, int wbase,
                                         const float4* ra, const float4* rw)
{
    #pragma unroll
    for (int p = 0; p < 4; p++)
        *reinterpret_cast<uint4*>(&As[wbase + p*32*ST]) =
            make_uint4(f2tf(ra[p].x), f2tf(ra[p].y), f2tf(ra[p].z), f2tf(ra[p].w));
    #pragma unroll
    for (int p = 0; p < 8; p++)
        *reinterpret_cast<uint4*>(&Ws[wbase + p*32*ST]) =
            make_uint4(f2tf(rw[p].x), f2tf(rw[p].y), f2tf(rw[p].z), f2tf(rw[p].w));
}

template<int MODE>
__global__ __launch_bounds__(256, 1) void gemm2_tf32(
    const float* __restrict__ A, const float* __restrict__ W,
    const float* __restrict__ bias, float* __restrict__ Cplain, int Ncols)
{
    extern __shared__ uint32_t sh[];

    const int tid  = threadIdx.x;
    const int lane = tid & 31, w = tid >> 5;
    const int g = lane >> 2, tg = lane & 3;
    const int wm = w & 1, wn = w >> 1;
    const int m0 = blockIdx.x << 7, n0 = blockIdx.y << 8;
    const int Kdim = Ec;

    float acc[4][8][4];
    #pragma unroll
    for (int i = 0; i < 4; i++)
        #pragma unroll
        for (int j = 0; j < 8; j++)
            #pragma unroll
            for (int r = 0; r < 4; r++) acc[i][j][r] = 0.0f;

    const int lr = tid >> 3;
    const int lc = (tid & 7) << 2;
    const float* Ap = A + (size_t)(m0 + lr) * Kdim + lc;
    const float* Wp = W + (size_t)(n0 + lr) * Kdim + lc;
    const int wbase = lr * ST + lc;

    float4 ra[4], rw[8];
    ld_chunk(Ap, Wp, Kdim, 0, ra, rw);
    st_chunk(sh, sh + 128*ST, wbase, ra, rw);
    __syncthreads();

    const int nch = Kdim / 32;
    for (int c = 0; c < nch; c++) {
        uint32_t* As = sh + (c & 1) * BUFW;
        uint32_t* Ws = As + 128*ST;
        const bool more = (c + 1 < nch);
        if (more) ld_chunk(Ap, Wp, Kdim, (c + 1) * 32, ra, rw);

        #pragma unroll
        for (int ks = 0; ks < 4; ks++) {
            const int kk = ks * 8;
            uint32_t bf[8][2];
            #pragma unroll
            for (int j = 0; j < 8; j++) {
                const int br = (wn*64 + j*8 + g)*ST + kk + tg;
                bf[j][0] = Ws[br]; bf[j][1] = Ws[br + 4];
            }
            #pragma unroll
            for (int i = 0; i < 4; i++) {
                const int ar = (wm*64 + i*16 + g)*ST + kk + tg;
                uint32_t a0 = As[ar],     a1 = As[ar + 8*ST];
                uint32_t a2 = As[ar + 4], a3 = As[ar + 8*ST + 4];
                #pragma unroll
                for (int j = 0; j < 8; j++)
                    mma8(acc[i][j], a0, a1, a2, a3, bf[j][0], bf[j][1]);
            }
        }

        if (more) {
            uint32_t* Asn = sh + ((c + 1) & 1) * BUFW;
            st_chunk(Asn, Asn + 128*ST, wbase, ra, rw);
            __syncthreads();
        }
    }

    #pragma unroll
    for (int i = 0; i < 4; i++) {
        const int mlo = m0 + wm*64 + i*16 + g;
        #pragma unroll
        for (int j = 0; j < 8; j++) {
            const int n = n0 + wn*64 + j*8 + 2*tg;
            const float b0 = __ldg(&bias[n]), b1 = __ldg(&bias[n+1]);
            #pragma unroll
            for (int half = 0; half < 2; half++) {
                const int m = mlo + half*8;
                const float v0 = acc[i][j][half*2+0] + b0;
                const float v1 = acc[i][j][half*2+1] + b1;
                if (MODE == 0) {
                    const int h = n / 192, r = n - h*192;
                    const int part = r >> 6, d = r & 63;
                    const int b = m >> 11, s = m & 2047;
                    float* dst = (part == 0) ? g_q : (part == 1) ? g_k : g_v;
                    *reinterpret_cast<float2*>(&dst[(((b*Hc + h)*Sc) + s)*HDc + d]) =
                        make_float2(v0, v1);
                } else {
                    *reinterpret_cast<float2*>(&Cplain[(size_t)m*Ncols + n]) =
                        make_float2(v0, v1);
                }
            }
        }
    }
}

// ===========================================================================
// Flash attention, tf32 mma.sync, 2 CTAs/SM version.
//   - Q tile lives in registers as pre-built A-fragments (pre-scaled by 1/8,
//     exact power-of-2 -> bit-identical S values).
//   - P C-fragment -> A-fragment via lane shuffles (exact; no smem, no sync).
//   - smem = K + V tiles only (34.8 KB static) -> 2 CTAs co-resident; one
//     CTA's MMA phase overlaps the other's load/softmax latency.
// Same mask/softmax math as the verified round-5 kernel (masks k <= q).
// ===========================================================================
#define AST 68
#define BQ  128
#define TK  64

__global__ __launch_bounds__(256, 2) void attn_tf32()
{
    __shared__ uint32_t Ks[TK*AST], Vs[TK*AST];

    const int tid  = threadIdx.x;
    const int lane = tid & 31, w = tid >> 5;
    const int g = lane >> 2, tg = lane & 3;
    const int jq = blockIdx.x;          // 0..15
    const int bh = blockIdx.y;          // 0..31

    const float* Qg = g_q + (size_t)bh * Sc * HDc;
    const float* Kg = g_k + (size_t)bh * Sc * HDc;
    const float* Vg = g_v + (size_t)bh * Sc * HDc;

    const int r0   = w * 16;
    const int qrow = jq*BQ + r0 + g;    // this thread's low row

    // Q A-fragments in registers, pre-scaled by 1/8 (exact)
    uint32_t qa[8][4];
    #pragma unroll
    for (int ks = 0; ks < 8; ks++) {
        const int c = ks*8 + tg;
        qa[ks][0] = f2tf(0.125f * __ldg(&Qg[(size_t)qrow*HDc + c]));
        qa[ks][1] = f2tf(0.125f * __ldg(&Qg[(size_t)(qrow+8)*HDc + c]));
        qa[ks][2] = f2tf(0.125f * __ldg(&Qg[(size_t)qrow*HDc + c + 4]));
        qa[ks][3] = f2tf(0.125f * __ldg(&Qg[(size_t)(qrow+8)*HDc + c + 4]));
    }

    float m_i[2] = {-INFINITY, -INFINITY};
    float l_i[2] = {0.0f, 0.0f};
    float O[8][4];
    #pragma unroll
    for (int j = 0; j < 8; j++)
        #pragma unroll
        for (int r = 0; r < 4; r++) O[j][r] = 0.0f;

    // shuffle sources for the P C-frag -> A-frag permutation
    const int srcA = (lane & ~3) | (tg >> 1);   // cols tg
    const int srcB = srcA + 2;                  // cols tg+4
    const bool odd = (tg & 1) != 0;

    const int kstart = (jq == (Sc/BQ - 1)) ? 0 : 2*jq;

    for (int jk = kstart; jk < Sc/TK; jk++) {
        __syncthreads();   // prior-iter smem reads done
        #pragma unroll
        for (int p = 0; p < 4; p++) {
            const int idx = tid + p*256;
            const int r = idx >> 4, c = (idx & 15) << 2;
            float4 kv = *reinterpret_cast<const float4*>(Kg + (size_t)(jk*TK + r)*HDc + c);
            float4 vv = *reinterpret_cast<const float4*>(Vg + (size_t)(jk*TK + r)*HDc + c);
            *reinterpret_cast<uint4*>(&Ks[r*AST + c]) =
                make_uint4(f2tf(kv.x), f2tf(kv.y), f2tf(kv.z), f2tf(kv.w));
            *reinterpret_cast<uint4*>(&Vs[r*AST + c]) =
                make_uint4(f2tf(vv.x), f2tf(vv.y), f2tf(vv.z), f2tf(vv.w));
        }
        __syncthreads();

        // S = (Q/8) K^T : warp rows r0..r0+15, all 64 cols (already scaled)
        float S[8][4];
        #pragma unroll
        for (int j = 0; j < 8; j++)
            #pragma unroll
            for (int r = 0; r < 4; r++) S[j][r] = 0.0f;

        #pragma unroll
        for (int ks = 0; ks < 8; ks++) {
            const int kk = ks*8;
            #pragma unroll
            for (int j = 0; j < 8; j++) {
                const int br = (j*8 + g)*AST + kk + tg;
                mma8(S[j], qa[ks][0], qa[ks][1], qa[ks][2], qa[ks][3],
                     Ks[br], Ks[br + 4]);
            }
        }

        // mask (tril incl diagonal gets -1e9; S already carries the 1/8 scale)
        const int qlo = qrow, qhi = qrow + 8;
        #pragma unroll
        for (int j = 0; j < 8; j++) {
            const int c0 = jk*TK + j*8 + 2*tg;
            S[j][0] += ((c0    ) <= qlo ? NEGBIG : 0.0f);
            S[j][1] += ((c0 + 1) <= qlo ? NEGBIG : 0.0f);
            S[j][2] += ((c0    ) <= qhi ? NEGBIG : 0.0f);
            S[j][3] += ((c0 + 1) <= qhi ? NEGBIG : 0.0f);
        }

        // online softmax (rows live in lanes sharing g; reduce over tg via xor)
        float rm0 = -INFINITY, rm1 = -INFINITY;
        #pragma unroll
        for (int j = 0; j < 8; j++) {
            rm0 = fmaxf(rm0, fmaxf(S[j][0], S[j][1]));
            rm1 = fmaxf(rm1, fmaxf(S[j][2], S[j][3]));
        }
        rm0 = fmaxf(rm0, __shfl_xor_sync(FULLM, rm0, 1));
        rm0 = fmaxf(rm0, __shfl_xor_sync(FULLM, rm0, 2));
        rm1 = fmaxf(rm1, __shfl_xor_sync(FULLM, rm1, 1));
        rm1 = fmaxf(rm1, __shfl_xor_sync(FULLM, rm1, 2));

        const float mn0 = fmaxf(m_i[0], rm0), mn1 = fmaxf(m_i[1], rm1);
        const float sc0 = __expf(m_i[0] - mn0), sc1 = __expf(m_i[1] - mn1);
        l_i[0] *= sc0; l_i[1] *= sc1;

        float rs0 = 0.0f, rs1 = 0.0f;
        #pragma unroll
        for (int j = 0; j < 8; j++) {
            O[j][0] *= sc0; O[j][1] *= sc0; O[j][2] *= sc1; O[j][3] *= sc1;
            S[j][0] = __expf(S[j][0] - mn0); rs0 += S[j][0];
            S[j][1] = __expf(S[j][1] - mn0); rs0 += S[j][1];
            S[j][2] = __expf(S[j][2] - mn1); rs1 += S[j][2];
            S[j][3] = __expf(S[j][3] - mn1); rs1 += S[j][3];
        }
        rs0 += __shfl_xor_sync(FULLM, rs0, 1);
        rs0 += __shfl_xor_sync(FULLM, rs0, 2);
        rs1 += __shfl_xor_sync(FULLM, rs1, 1);
        rs1 += __shfl_xor_sync(FULLM, rs1, 2);
        l_i[0] += rs0; l_i[1] += rs1;
        m_i[0] = mn0;  m_i[1] = mn1;

        // O += P V : per k-group, permute P C-frag -> A-frag via shuffles.
        //   pa0 = P(g, 8js+tg)  pa1 = P(g+8, 8js+tg)
        //   pa2 = P(g, 8js+tg+4) pa3 = P(g+8, 8js+tg+4)
        // source lane 4g|(tg>>1) holds cols 2(tg>>1)(+1); parity selects elem.
        #pragma unroll
        for (int js = 0; js < 8; js++) {
            const uint32_t t0 = f2tf(S[js][0]), t1 = f2tf(S[js][1]);
            const uint32_t t2 = f2tf(S[js][2]), t3 = f2tf(S[js][3]);
            const uint32_t u0 = __shfl_sync(FULLM, t0, srcA);
            const uint32_t u1 = __shfl_sync(FULLM, t1, srcA);
            const uint32_t u2 = __shfl_sync(FULLM, t2, srcA);
            const uint32_t u3 = __shfl_sync(FULLM, t3, srcA);
            const uint32_t v0 = __shfl_sync(FULLM, t0, srcB);
            const uint32_t v1 = __shfl_sync(FULLM, t1, srcB);
            const uint32_t v2 = __shfl_sync(FULLM, t2, srcB);
            const uint32_t v3 = __shfl_sync(FULLM, t3, srcB);
            const uint32_t pa0 = odd ? u1 : u0;
            const uint32_t pa1 = odd ? u3 : u2;
            const uint32_t pa2 = odd ? v1 : v0;
            const uint32_t pa3 = odd ? v3 : v2;
            const int kk = js*8;
            #pragma unroll
            for (int j = 0; j < 8; j++) {
                const int nb = j*8 + g;
                mma8(O[j], pa0, pa1, pa2, pa3,
                     Vs[(kk + tg)*AST + nb], Vs[(kk + tg + 4)*AST + nb]);
            }
        }
    }

    // normalize + store to g_vals [B,S,E], E index = h*64 + d
    const int b = bh >> 4, h = bh & 15;
    const float inv0 = 1.0f / l_i[0], inv1 = 1.0f / l_i[1];
    const size_t base0 = ((size_t)(b*Sc + qrow))*Ec + h*HDc;
    const size_t base1 = ((size_t)(b*Sc + qrow + 8))*Ec + h*HDc;
    #pragma unroll
    for (int j = 0; j < 8; j++) {
        const int c = j*8 + 2*tg;
        *reinterpret_cast<float2*>(&g_vals[base0 + c]) =
            make_float2(O[j][0]*inv0, O[j][1]*inv0);
        *reinterpret_cast<float2*>(&g_vals[base1 + c]) =
            make_float2(O[j][2]*inv1, O[j][3]*inv1);
    }
}

// ---------------------------------------------------------------------------
extern "C" void kernel_launch(void* const* d_in, const int* in_sizes, int n_in,
                              void* d_out, int out_size)
{
    const float* x    = (const float*)d_in[0];
    const float* Wqkv = (const float*)d_in[1];
    const float* bqkv = (const float*)d_in[2];
    const float* Wout = (const float*)d_in[3];
    const float* bout = (const float*)d_in[4];
    float* out = (float*)d_out;

    float* valsp = nullptr;
    cudaGetSymbolAddress((void**)&valsp, g_vals);

    cudaFuncSetAttribute(gemm2_tf32<0>,
                         cudaFuncAttributeMaxDynamicSharedMemorySize, G2_SMEM);
    cudaFuncSetAttribute(gemm2_tf32<1>,
                         cudaFuncAttributeMaxDynamicSharedMemorySize, G2_SMEM);

    // 1) QKV projection (plain tf32, 128x256 tiles) -> scatter into g_q/g_k/g_v
    gemm2_tf32<0><<<dim3(Mrows/128, (3*Ec)/256), 256, G2_SMEM>>>(
        x, Wqkv, bqkv, nullptr, 0);

    // 2) Attention -> g_vals [B,S,E]  (static smem, 2 CTAs/SM)
    attn_tf32<<<dim3(Sc/BQ, Bc*Hc), 256>>>();

    // 3) Output projection (plain tf32) -> d_out
    gemm2_tf32<1><<<dim3(Mrows/128, Ec/256), 256, G2_SMEM>>>(
        valsp, Wout, bout, out, Ec);
}

// round 15
// speedup vs baseline: 3.4927x; 1.0638x over previous
#include <cuda_runtime.h>
#include <cuda_bf16.h>
#include <math.h>
#include <stdint.h>

// Problem constants
#define Bc   2
#define Sc   2048
#define Ec   1024
#define Hc   16
#define HDc  64
#define Mrows (Bc*Sc)          // 4096
#define NEGBIG (-1.0e9f)
#define FULLM 0xffffffffu

// Scratch (device globals; no allocation allowed)
__device__ float g_q[Bc*Hc*Sc*HDc];     // [B,H,S,HD]
__device__ float g_k[Bc*Hc*Sc*HDc];
__device__ float g_v[Bc*Hc*Sc*HDc];
__device__ float g_vals[Mrows*Ec];      // [B,S,E]

// ---------------------------------------------------------------------------
// mma.sync helpers
// ---------------------------------------------------------------------------
__device__ __forceinline__ uint32_t f2tf(float x) {
    uint32_t r;
    asm("cvt.rna.tf32.f32 %0, %1;" : "=r"(r) : "f"(x));
    return r;
}
__device__ __forceinline__ void mma8(float* c,
    uint32_t a0, uint32_t a1, uint32_t a2, uint32_t a3,
    uint32_t b0, uint32_t b1)
{
    asm volatile(
        "mma.sync.aligned.m16n8k8.row.col.f32.tf32.tf32.f32 "
        "{%0,%1,%2,%3},{%4,%5,%6,%7},{%8,%9},{%0,%1,%2,%3};"
        : "+f"(c[0]), "+f"(c[1]), "+f"(c[2]), "+f"(c[3])
        : "r"(a0), "r"(a1), "r"(a2), "r"(a3), "r"(b0), "r"(b1));
}

// ===========================================================================
// Unified plain-tf32 GEMM (unchanged from round 12; verified).
// Block tile 128(M) x 256(N), K-chunk 32, 8 warps, warp tile 64x64,
// double-buffered smem + register-staged gmem prefetch.
// MODE 0: scatter epilogue into g_q/g_k/g_v; MODE 1: plain row-major store.
// ===========================================================================
#define ST   36
#define BUFW (384*ST)
#define G2_SMEM (2*BUFW*4)

__device__ __forceinline__ void ld_chunk(const float* Ap, const float* Wp,
                                         int Kd, int koff,
                                         float4* ra, float4* rw)
{
    #pragma unroll
    for (int p = 0; p < 4; p++)
        ra[p] = *reinterpret_cast<const float4*>(Ap + (size_t)p*32*Kd + koff);
    #pragma unroll
    for (int p = 0; p < 8; p++)
        rw[p] = *reinterpret_cast<const float4*>(Wp + (size_t)p*32*Kd + koff);
}
__device__ __forceinline__ void st_chunk(uint32_t* As, uint32_t* Ws, int wbase,
                                         const float4* ra, const float4* rw)
{
    #pragma unroll
    for (int p = 0; p < 4; p++)
        *reinterpret_cast<uint4*>(&As[wbase + p*32*ST]) =
            make_uint4(f2tf(ra[p].x), f2tf(ra[p].y), f2tf(ra[p].z), f2tf(ra[p].w));
    #pragma unroll
    for (int p = 0; p < 8; p++)
        *reinterpret_cast<uint4*>(&Ws[wbase + p*32*ST]) =
            make_uint4(f2tf(rw[p].x), f2tf(rw[p].y), f2tf(rw[p].z), f2tf(rw[p].w));
}

template<int MODE>
__global__ __launch_bounds__(256, 1) void gemm2_tf32(
    const float* __restrict__ A, const float* __restrict__ W,
    const float* __restrict__ bias, float* __restrict__ Cplain, int Ncols)
{
    extern __shared__ uint32_t sh[];

    const int tid  = threadIdx.x;
    const int lane = tid & 31, w = tid >> 5;
    const int g = lane >> 2, tg = lane & 3;
    const int wm = w & 1, wn = w >> 1;
    const int m0 = blockIdx.x << 7, n0 = blockIdx.y << 8;
    const int Kdim = Ec;

    float acc[4][8][4];
    #pragma unroll
    for (int i = 0; i < 4; i++)
        #pragma unroll
        for (int j = 0; j < 8; j++)
            #pragma unroll
            for (int r = 0; r < 4; r++) acc[i][j][r] = 0.0f;

    const int lr = tid >> 3;
    const int lc = (tid & 7) << 2;
    const float* Ap = A + (size_t)(m0 + lr) * Kdim + lc;
    const float* Wp = W + (size_t)(n0 + lr) * Kdim + lc;
    const int wbase = lr * ST + lc;

    float4 ra[4], rw[8];
    ld_chunk(Ap, Wp, Kdim, 0, ra, rw);
    st_chunk(sh, sh + 128*ST, wbase, ra, rw);
    __syncthreads();

    const int nch = Kdim / 32;
    for (int c = 0; c < nch; c++) {
        uint32_t* As = sh + (c & 1) * BUFW;
        uint32_t* Ws = As + 128*ST;
        const bool more = (c + 1 < nch);
        if (more) ld_chunk(Ap, Wp, Kdim, (c + 1) * 32, ra, rw);

        #pragma unroll
        for (int ks = 0; ks < 4; ks++) {
            const int kk = ks * 8;
            uint32_t bf[8][2];
            #pragma unroll
            for (int j = 0; j < 8; j++) {
                const int br = (wn*64 + j*8 + g)*ST + kk + tg;
                bf[j][0] = Ws[br]; bf[j][1] = Ws[br + 4];
            }
            #pragma unroll
            for (int i = 0; i < 4; i++) {
                const int ar = (wm*64 + i*16 + g)*ST + kk + tg;
                uint32_t a0 = As[ar],     a1 = As[ar + 8*ST];
                uint32_t a2 = As[ar + 4], a3 = As[ar + 8*ST + 4];
                #pragma unroll
                for (int j = 0; j < 8; j++)
                    mma8(acc[i][j], a0, a1, a2, a3, bf[j][0], bf[j][1]);
            }
        }

        if (more) {
            uint32_t* Asn = sh + ((c + 1) & 1) * BUFW;
            st_chunk(Asn, Asn + 128*ST, wbase, ra, rw);
            __syncthreads();
        }
    }

    #pragma unroll
    for (int i = 0; i < 4; i++) {
        const int mlo = m0 + wm*64 + i*16 + g;
        #pragma unroll
        for (int j = 0; j < 8; j++) {
            const int n = n0 + wn*64 + j*8 + 2*tg;
            const float b0 = __ldg(&bias[n]), b1 = __ldg(&bias[n+1]);
            #pragma unroll
            for (int half = 0; half < 2; half++) {
                const int m = mlo + half*8;
                const float v0 = acc[i][j][half*2+0] + b0;
                const float v1 = acc[i][j][half*2+1] + b1;
                if (MODE == 0) {
                    const int h = n / 192, r = n - h*192;
                    const int part = r >> 6, d = r & 63;
                    const int b = m >> 11, s = m & 2047;
                    float* dst = (part == 0) ? g_q : (part == 1) ? g_k : g_v;
                    *reinterpret_cast<float2*>(&dst[(((b*Hc + h)*Sc) + s)*HDc + d]) =
                        make_float2(v0, v1);
                } else {
                    *reinterpret_cast<float2*>(&Cplain[(size_t)m*Ncols + n]) =
                        make_float2(v0, v1);
                }
            }
        }
    }
}

// ===========================================================================
// Flash attention, tf32 mma.sync.
//   - Q tile in smem, pre-scaled by 1/8 at store (exact power of 2 ->
//     bit-identical S). No qa registers -> live set ~90 regs -> no spill
//     at the 128-reg cap from launch_bounds(256, 2).
//   - K/V prefetched into registers BEFORE the barrier: LDG latency overlaps
//     the barrier wait + previous tile's in-flight MMAs.
//   - P C-frag -> A-frag via lane shuffles (exact; no smem, no syncwarp).
//   - smem = Q + K + V = 69,632 B dynamic -> 2 CTAs/SM (139 KB < 227 KB).
//   - q-tiles launched in descending-work order (32-tile CTAs first).
// Mask semantics identical to the verified kernels (masks k <= q).
// ===========================================================================
#define AST 68
#define BQ  128
#define TK  64
#define ATTN_SMEM ((BQ + TK + TK) * AST * 4)   // 69,632 B

__global__ __launch_bounds__(256, 2) void attn_tf32()
{
    extern __shared__ uint32_t sm[];
    uint32_t* Qs = sm;                  // BQ*AST
    uint32_t* Ks = Qs + BQ*AST;         // TK*AST
    uint32_t* Vs = Ks + TK*AST;         // TK*AST

    const int tid  = threadIdx.x;
    const int lane = tid & 31, w = tid >> 5;
    const int g = lane >> 2, tg = lane & 3;
    const int bx = blockIdx.x;
    // descending-work order: heavy tiles (jq=15: full scan, jq=0: 32 tiles) first
    const int jq = (bx == 0) ? (Sc/BQ - 1) : bx - 1;
    const int bh = blockIdx.y;          // 0..31

    const float* Qg = g_q + (size_t)bh * Sc * HDc;
    const float* Kg = g_k + (size_t)bh * Sc * HDc;
    const float* Vg = g_v + (size_t)bh * Sc * HDc;

    // Load Q tile (128 x 64), pre-scaled by 1/8 (exact)
    #pragma unroll
    for (int p = 0; p < 8; p++) {
        const int idx = tid + p*256;
        const int r = idx >> 4, c = (idx & 15) << 2;
        float4 v = *reinterpret_cast<const float4*>(Qg + (size_t)(jq*BQ + r)*HDc + c);
        *reinterpret_cast<uint4*>(&Qs[r*AST + c]) =
            make_uint4(f2tf(0.125f*v.x), f2tf(0.125f*v.y),
                       f2tf(0.125f*v.z), f2tf(0.125f*v.w));
    }

    float m_i[2] = {-INFINITY, -INFINITY};
    float l_i[2] = {0.0f, 0.0f};
    float O[8][4];
    #pragma unroll
    for (int j = 0; j < 8; j++)
        #pragma unroll
        for (int r = 0; r < 4; r++) O[j][r] = 0.0f;

    const int r0   = w * 16;
    const int qrow = jq*BQ + r0 + g;

    // shuffle sources for the P C-frag -> A-frag permutation
    const int srcA = (lane & ~3) | (tg >> 1);   // cols tg
    const int srcB = srcA + 2;                  // cols tg+4
    const bool odd = (tg & 1) != 0;

    const int kstart = (jq == (Sc/BQ - 1)) ? 0 : 2*jq;

    for (int jk = kstart; jk < Sc/TK; jk++) {
        // Prefetch K/V tile into registers BEFORE the barrier — LDG latency
        // overlaps the barrier wait and the previous tile's in-flight MMAs.
        float4 kreg[4], vreg[4];
        #pragma unroll
        for (int p = 0; p < 4; p++) {
            const int idx = tid + p*256;
            const int r = idx >> 4, c = (idx & 15) << 2;
            kreg[p] = *reinterpret_cast<const float4*>(Kg + (size_t)(jk*TK + r)*HDc + c);
            vreg[p] = *reinterpret_cast<const float4*>(Vg + (size_t)(jk*TK + r)*HDc + c);
        }
        __syncthreads();   // prior-iter smem reads done (covers Q store on iter 1)
        #pragma unroll
        for (int p = 0; p < 4; p++) {
            const int idx = tid + p*256;
            const int r = idx >> 4, c = (idx & 15) << 2;
            *reinterpret_cast<uint4*>(&Ks[r*AST + c]) =
                make_uint4(f2tf(kreg[p].x), f2tf(kreg[p].y),
                           f2tf(kreg[p].z), f2tf(kreg[p].w));
            *reinterpret_cast<uint4*>(&Vs[r*AST + c]) =
                make_uint4(f2tf(vreg[p].x), f2tf(vreg[p].y),
                           f2tf(vreg[p].z), f2tf(vreg[p].w));
        }
        __syncthreads();

        // S = (Q/8) K^T : warp rows r0..r0+15, all 64 cols (already scaled)
        float S[8][4];
        #pragma unroll
        for (int j = 0; j < 8; j++)
            #pragma unroll
            for (int r = 0; r < 4; r++) S[j][r] = 0.0f;

        #pragma unroll
        for (int ks = 0; ks < 8; ks++) {
            const int kk = ks*8;
            const int ar = (r0 + g)*AST + kk + tg;
            const uint32_t a0 = Qs[ar],     a1 = Qs[ar + 8*AST];
            const uint32_t a2 = Qs[ar + 4], a3 = Qs[ar + 8*AST + 4];
            #pragma unroll
            for (int j = 0; j < 8; j++) {
                const int br = (j*8 + g)*AST + kk + tg;
                mma8(S[j], a0, a1, a2, a3, Ks[br], Ks[br + 4]);
            }
        }

        // mask (tril incl diagonal gets -1e9; S already carries the 1/8 scale)
        const int qlo = qrow, qhi = qrow + 8;
        #pragma unroll
        for (int j = 0; j < 8; j++) {
            const int c0 = jk*TK + j*8 + 2*tg;
            S[j][0] += ((c0    ) <= qlo ? NEGBIG : 0.0f);
            S[j][1] += ((c0 + 1) <= qlo ? NEGBIG : 0.0f);
            S[j][2] += ((c0    ) <= qhi ? NEGBIG : 0.0f);
            S[j][3] += ((c0 + 1) <= qhi ? NEGBIG : 0.0f);
        }

        // online softmax (rows live in lanes sharing g; reduce over tg via xor)
        float rm0 = -INFINITY, rm1 = -INFINITY;
        #pragma unroll
        for (int j = 0; j < 8; j++) {
            rm0 = fmaxf(rm0, fmaxf(S[j][0], S[j][1]));
            rm1 = fmaxf(rm1, fmaxf(S[j][2], S[j][3]));
        }
        rm0 = fmaxf(rm0, __shfl_xor_sync(FULLM, rm0, 1));
        rm0 = fmaxf(rm0, __shfl_xor_sync(FULLM, rm0, 2));
        rm1 = fmaxf(rm1, __shfl_xor_sync(FULLM, rm1, 1));
        rm1 = fmaxf(rm1, __shfl_xor_sync(FULLM, rm1, 2));

        const float mn0 = fmaxf(m_i[0], rm0), mn1 = fmaxf(m_i[1], rm1);
        const float sc0 = __expf(m_i[0] - mn0), sc1 = __expf(m_i[1] - mn1);
        l_i[0] *= sc0; l_i[1] *= sc1;

        float rs0 = 0.0f, rs1 = 0.0f;
        #pragma unroll
        for (int j = 0; j < 8; j++) {
            O[j][0] *= sc0; O[j][1] *= sc0; O[j][2] *= sc1; O[j][3] *= sc1;
            S[j][0] = __expf(S[j][0] - mn0); rs0 += S[j][0];
            S[j][1] = __expf(S[j][1] - mn0); rs0 += S[j][1];
            S[j][2] = __expf(S[j][2] - mn1); rs1 += S[j][2];
            S[j][3] = __expf(S[j][3] - mn1); rs1 += S[j][3];
        }
        rs0 += __shfl_xor_sync(FULLM, rs0, 1);
        rs0 += __shfl_xor_sync(FULLM, rs0, 2);
        rs1 += __shfl_xor_sync(FULLM, rs1, 1);
        rs1 += __shfl_xor_sync(FULLM, rs1, 2);
        l_i[0] += rs0; l_i[1] += rs1;
        m_i[0] = mn0;  m_i[1] = mn1;

        // O += P V : per k-group, permute P C-frag -> A-frag via shuffles.
        #pragma unroll
        for (int js = 0; js < 8; js++) {
            const uint32_t t0 = f2tf(S[js][0]), t1 = f2tf(S[js][1]);
            const uint32_t t2 = f2tf(S[js][2]), t3 = f2tf(S[js][3]);
            const uint32_t u0 = __shfl_sync(FULLM, t0, srcA);
            const uint32_t u1 = __shfl_sync(FULLM, t1, srcA);
            const uint32_t u2 = __shfl_sync(FULLM, t2, srcA);
            const uint32_t u3 = __shfl_sync(FULLM, t3, srcA);
            const uint32_t v0 = __shfl_sync(FULLM, t0, srcB);
            const uint32_t v1 = __shfl_sync(FULLM, t1, srcB);
            const uint32_t v2 = __shfl_sync(FULLM, t2, srcB);
            const uint32_t v3 = __shfl_sync(FULLM, t3, srcB);
            const uint32_t pa0 = odd ? u1 : u0;
            const uint32_t pa1 = odd ? u3 : u2;
            const uint32_t pa2 = odd ? v1 : v0;
            const uint32_t pa3 = odd ? v3 : v2;
            const int kk = js*8;
            #pragma unroll
            for (int j = 0; j < 8; j++) {
                const int nb = j*8 + g;
                mma8(O[j], pa0, pa1, pa2, pa3,
                     Vs[(kk + tg)*AST + nb], Vs[(kk + tg + 4)*AST + nb]);
            }
        }
    }

    // normalize + store to g_vals [B,S,E], E index = h*64 + d
    const int b = bh >> 4, h = bh & 15;
    const float inv0 = 1.0f / l_i[0], inv1 = 1.0f / l_i[1];
    const size_t base0 = ((size_t)(b*Sc + qrow))*Ec + h*HDc;
    const size_t base1 = ((size_t)(b*Sc + qrow + 8))*Ec + h*HDc;
    #pragma unroll
    for (int j = 0; j < 8; j++) {
        const int c = j*8 + 2*tg;
        *reinterpret_cast<float2*>(&g_vals[base0 + c]) =
            make_float2(O[j][0]*inv0, O[j][1]*inv0);
        *reinterpret_cast<float2*>(&g_vals[base1 + c]) =
            make_float2(O[j][2]*inv1, O[j][3]*inv1);
    }
}

// ---------------------------------------------------------------------------
extern "C" void kernel_launch(void* const* d_in, const int* in_sizes, int n_in,
                              void* d_out, int out_size)
{
    const float* x    = (const float*)d_in[0];
    const float* Wqkv = (const float*)d_in[1];
    const float* bqkv = (const float*)d_in[2];
    const float* Wout = (const float*)d_in[3];
    const float* bout = (const float*)d_in[4];
    float* out = (float*)d_out;

    float* valsp = nullptr;
    cudaGetSymbolAddress((void**)&valsp, g_vals);

    cudaFuncSetAttribute(gemm2_tf32<0>,
                         cudaFuncAttributeMaxDynamicSharedMemorySize, G2_SMEM);
    cudaFuncSetAttribute(gemm2_tf32<1>,
                         cudaFuncAttributeMaxDynamicSharedMemorySize, G2_SMEM);
    cudaFuncSetAttribute(attn_tf32,
                         cudaFuncAttributeMaxDynamicSharedMemorySize, ATTN_SMEM);

    // 1) QKV projection (plain tf32, 128x256 tiles) -> scatter into g_q/g_k/g_v
    gemm2_tf32<0><<<dim3(Mrows/128, (3*Ec)/256), 256, G2_SMEM>>>(
        x, Wqkv, bqkv, nullptr, 0);

    // 2) Attention -> g_vals [B,S,E]  (2 CTAs/SM, prefetch + work-desc order)
    attn_tf32<<<dim3(Sc/BQ, Bc*Hc), 256, ATTN_SMEM>>>();

    // 3) Output projection (plain tf32) -> d_out
    gemm2_tf32<1><<<dim3(Mrows/128, Ec/256), 256, G2_SMEM>>>(
        valsp, Wout, bout, out, Ec);
}